// round 4
// baseline (speedup 1.0000x reference)
#include <cuda_runtime.h>

#define NN 100000
#define FF 64
#define HH 8
#define DD 8
#define EE 1200000
#define HID 32

// scratch (allocation-free rule: __device__ globals)
__device__ float g_src_buf[NN * FF];
__device__ float g_dst_buf[NN * FF];
__device__ int g_idx_is64;

__device__ __forceinline__ float leaky(float x) { return fmaxf(x, 0.2f * x); }
__device__ __forceinline__ float sigm(float x) { return 1.0f / (1.0f + __expf(-x)); }

__device__ __forceinline__ void red4(float* p, float x, float y, float z, float w) {
    asm volatile("red.global.add.v4.f32 [%0], {%1,%2,%3,%4};"
                 :: "l"(p), "f"(x), "f"(y), "f"(z), "f"(w) : "memory");
}

// ---------------------------------------------------------------------------
// Node kernel: g_src = h@W_src+b, g_dst = h@W_dst+b, out = sigmoid(mlp(g_dst))*g_dst
// Block 0 / thread 0 additionally probes edge_index dtype (int64 vs int32):
// values < 1e5, so if int64 every odd 32-bit word of the first 8 entries is 0.
__global__ __launch_bounds__(128) void node_kernel(
    const float* __restrict__ h,
    const float* __restrict__ W_src, const float* __restrict__ b_src,
    const float* __restrict__ W_dst, const float* __restrict__ b_dst,
    const float* __restrict__ Wa1, const float* __restrict__ ba1,
    const float* __restrict__ Wa2, const float* __restrict__ ba2,
    const unsigned int* __restrict__ eidx_words,
    float* __restrict__ out)
{
    __shared__ float WsT[FF * FF];    // [j][k]
    __shared__ float WdT[FF * FF];
    __shared__ float W1T[HID * FF];   // [j][k]
    __shared__ float W2T[HH * HID];   // [t][j]
    __shared__ float bs[FF], bd[FF], b1[HID], b2[HH];

    int tid = threadIdx.x;
    if (blockIdx.x == 0 && tid == 0) {
        int is64 = 1;
        for (int i = 0; i < 8; i++)
            if (eidx_words[2 * i + 1] != 0u) is64 = 0;
        g_idx_is64 = is64;
    }
    for (int i = tid; i < FF * FF; i += 128) {
        int k = i >> 6, j = i & 63;
        WsT[j * FF + k] = W_src[i];
        WdT[j * FF + k] = W_dst[i];
    }
    for (int i = tid; i < HID * FF; i += 128) {
        int k = i / HID, j = i % HID;     // Wa1 is [F][HID]
        W1T[j * FF + k] = Wa1[i];
    }
    for (int i = tid; i < HH * HID; i += 128) {
        int k = i / HH, j = i % HH;       // Wa2 is [HID][H]
        W2T[j * HID + k] = Wa2[i];
    }
    if (tid < FF) { bs[tid] = b_src[tid]; bd[tid] = b_dst[tid]; }
    if (tid < HID) b1[tid] = ba1[tid];
    if (tid < HH)  b2[tid] = ba2[tid];
    __syncthreads();

    int node = blockIdx.x * 128 + tid;
    if (node >= NN) return;

    float hr[FF];
    {
        const float4* hp = (const float4*)(h + (size_t)node * FF);
        #pragma unroll
        for (int k4 = 0; k4 < FF / 4; k4++) {
            float4 v = hp[k4];
            hr[4 * k4 + 0] = v.x; hr[4 * k4 + 1] = v.y;
            hr[4 * k4 + 2] = v.z; hr[4 * k4 + 3] = v.w;
        }
    }

    // g_src -> gmem (not kept)
    {
        float4* gp = (float4*)(g_src_buf + (size_t)node * FF);
        #pragma unroll
        for (int j = 0; j < FF; j += 4) {
            float a0 = bs[j], a1 = bs[j + 1], a2 = bs[j + 2], a3 = bs[j + 3];
            #pragma unroll
            for (int k = 0; k < FF; k += 4) {
                float4 w0 = *(const float4*)&WsT[(j + 0) * FF + k];
                float4 w1 = *(const float4*)&WsT[(j + 1) * FF + k];
                float4 w2 = *(const float4*)&WsT[(j + 2) * FF + k];
                float4 w3 = *(const float4*)&WsT[(j + 3) * FF + k];
                a0 += hr[k] * w0.x + hr[k + 1] * w0.y + hr[k + 2] * w0.z + hr[k + 3] * w0.w;
                a1 += hr[k] * w1.x + hr[k + 1] * w1.y + hr[k + 2] * w1.z + hr[k + 3] * w1.w;
                a2 += hr[k] * w2.x + hr[k + 1] * w2.y + hr[k + 2] * w2.z + hr[k + 3] * w2.w;
                a3 += hr[k] * w3.x + hr[k + 1] * w3.y + hr[k + 2] * w3.z + hr[k + 3] * w3.w;
            }
            gp[j >> 2] = make_float4(a0, a1, a2, a3);
        }
    }

    // g_dst -> regs + gmem
    float gd[FF];
    {
        float4* gp = (float4*)(g_dst_buf + (size_t)node * FF);
        #pragma unroll
        for (int j = 0; j < FF; j += 4) {
            float a0 = bd[j], a1 = bd[j + 1], a2 = bd[j + 2], a3 = bd[j + 3];
            #pragma unroll
            for (int k = 0; k < FF; k += 4) {
                float4 w0 = *(const float4*)&WdT[(j + 0) * FF + k];
                float4 w1 = *(const float4*)&WdT[(j + 1) * FF + k];
                float4 w2 = *(const float4*)&WdT[(j + 2) * FF + k];
                float4 w3 = *(const float4*)&WdT[(j + 3) * FF + k];
                a0 += hr[k] * w0.x + hr[k + 1] * w0.y + hr[k + 2] * w0.z + hr[k + 3] * w0.w;
                a1 += hr[k] * w1.x + hr[k + 1] * w1.y + hr[k + 2] * w1.z + hr[k + 3] * w1.w;
                a2 += hr[k] * w2.x + hr[k + 1] * w2.y + hr[k + 2] * w2.z + hr[k + 3] * w2.w;
                a3 += hr[k] * w3.x + hr[k + 1] * w3.y + hr[k + 2] * w3.z + hr[k + 3] * w3.w;
            }
            gd[j + 0] = a0; gd[j + 1] = a1; gd[j + 2] = a2; gd[j + 3] = a3;
            gp[j >> 2] = make_float4(a0, a1, a2, a3);
        }
    }

    // attention MLP on g_dst (reuse hr registers for leaky(g_dst))
    #pragma unroll
    for (int k = 0; k < FF; k++) hr[k] = leaky(gd[k]);

    float y1[HID];
    #pragma unroll
    for (int j = 0; j < HID; j += 4) {
        float a0 = b1[j], a1 = b1[j + 1], a2 = b1[j + 2], a3 = b1[j + 3];
        #pragma unroll
        for (int k = 0; k < FF; k += 4) {
            float4 w0 = *(const float4*)&W1T[(j + 0) * FF + k];
            float4 w1 = *(const float4*)&W1T[(j + 1) * FF + k];
            float4 w2 = *(const float4*)&W1T[(j + 2) * FF + k];
            float4 w3 = *(const float4*)&W1T[(j + 3) * FF + k];
            a0 += hr[k] * w0.x + hr[k + 1] * w0.y + hr[k + 2] * w0.z + hr[k + 3] * w0.w;
            a1 += hr[k] * w1.x + hr[k + 1] * w1.y + hr[k + 2] * w1.z + hr[k + 3] * w1.w;
            a2 += hr[k] * w2.x + hr[k + 1] * w2.y + hr[k + 2] * w2.z + hr[k + 3] * w2.w;
            a3 += hr[k] * w3.x + hr[k + 1] * w3.y + hr[k + 2] * w3.z + hr[k + 3] * w3.w;
        }
        y1[j + 0] = leaky(a0); y1[j + 1] = leaky(a1);
        y1[j + 2] = leaky(a2); y1[j + 3] = leaky(a3);
    }

    float att[HH];
    #pragma unroll
    for (int t = 0; t < HH; t++) {
        float a = b2[t];
        #pragma unroll
        for (int j = 0; j < HID; j += 4) {
            float4 w = *(const float4*)&W2T[t * HID + j];
            a += y1[j] * w.x + y1[j + 1] * w.y + y1[j + 2] * w.z + y1[j + 3] * w.w;
        }
        att[t] = sigm(a);
    }

    // out = a_dst * g_dst  (initializes output; edge kernel atomically adds)
    float4* op = (float4*)(out + (size_t)node * FF);
    #pragma unroll
    for (int t = 0; t < HH; t++) {
        float a = att[t];
        op[2 * t + 0] = make_float4(a * gd[t * 8 + 0], a * gd[t * 8 + 1],
                                    a * gd[t * 8 + 2], a * gd[t * 8 + 3]);
        op[2 * t + 1] = make_float4(a * gd[t * 8 + 4], a * gd[t * 8 + 5],
                                    a * gd[t * 8 + 6], a * gd[t * 8 + 7]);
    }
}

// ---------------------------------------------------------------------------
// Edge kernel: msg = g_src[src]+g_dst[dst]; a = sigmoid(mlp(msg));
// out[dst] += a[h] * g_src[src] (per head)
// Register-lean variant: do NOT keep msg_src; reload the src row (L1/L2 hit)
// after the MLP for the reduce. Cap regs at 128 -> >=4 CTAs/SM.
__global__ __launch_bounds__(128, 4) void edge_kernel(
    const void* __restrict__ edge_index,
    const float* __restrict__ Wa1, const float* __restrict__ ba1,
    const float* __restrict__ Wa2, const float* __restrict__ ba2,
    float* __restrict__ out)
{
    __shared__ float W1T[HID * FF];
    __shared__ float W2T[HH * HID];
    __shared__ float b1[HID], b2[HH];

    int tid = threadIdx.x;
    for (int i = tid; i < HID * FF; i += 128) {
        int k = i / HID, j = i % HID;     // Wa1_src is [F][HID]
        W1T[j * FF + k] = Wa1[i];
    }
    for (int i = tid; i < HH * HID; i += 128) {
        int k = i / HH, j = i % HH;       // Wa2_src is [HID][H]
        W2T[j * HID + k] = Wa2[i];
    }
    if (tid < HID) b1[tid] = ba1[tid];
    if (tid < HH)  b2[tid] = ba2[tid];
    __syncthreads();

    int e = blockIdx.x * 128 + tid;
    if (e >= EE) return;

    long long src, dst;
    if (g_idx_is64) {
        const long long* ei = (const long long*)edge_index;
        src = ei[e]; dst = ei[EE + e];
    } else {
        const int* ei = (const int*)edge_index;
        src = ei[e]; dst = ei[EE + e];
    }

    const float4* sp = (const float4*)(g_src_buf + src * FF);
    const float4* dp = (const float4*)(g_dst_buf + dst * FF);

    float lm[FF];   // leaky(msg) only; msg_src reloaded later
    #pragma unroll
    for (int k4 = 0; k4 < FF / 4; k4++) {
        float4 a = sp[k4];
        float4 b = dp[k4];
        lm[4 * k4 + 0] = leaky(a.x + b.x);
        lm[4 * k4 + 1] = leaky(a.y + b.y);
        lm[4 * k4 + 2] = leaky(a.z + b.z);
        lm[4 * k4 + 3] = leaky(a.w + b.w);
    }

    float y1[HID];
    #pragma unroll
    for (int j = 0; j < HID; j += 4) {
        float a0 = b1[j], a1 = b1[j + 1], a2 = b1[j + 2], a3 = b1[j + 3];
        #pragma unroll
        for (int k = 0; k < FF; k += 4) {
            float4 w0 = *(const float4*)&W1T[(j + 0) * FF + k];
            float4 w1 = *(const float4*)&W1T[(j + 1) * FF + k];
            float4 w2 = *(const float4*)&W1T[(j + 2) * FF + k];
            float4 w3 = *(const float4*)&W1T[(j + 3) * FF + k];
            a0 += lm[k] * w0.x + lm[k + 1] * w0.y + lm[k + 2] * w0.z + lm[k + 3] * w0.w;
            a1 += lm[k] * w1.x + lm[k + 1] * w1.y + lm[k + 2] * w1.z + lm[k + 3] * w1.w;
            a2 += lm[k] * w2.x + lm[k + 1] * w2.y + lm[k + 2] * w2.z + lm[k + 3] * w2.w;
            a3 += lm[k] * w3.x + lm[k + 1] * w3.y + lm[k + 2] * w3.z + lm[k + 3] * w3.w;
        }
        y1[j + 0] = leaky(a0); y1[j + 1] = leaky(a1);
        y1[j + 2] = leaky(a2); y1[j + 3] = leaky(a3);
    }

    float att[HH];
    #pragma unroll
    for (int t = 0; t < HH; t++) {
        float a = b2[t];
        #pragma unroll
        for (int j = 0; j < HID; j += 4) {
            float4 w = *(const float4*)&W2T[t * HID + j];
            a += y1[j] * w.x + y1[j + 1] * w.y + y1[j + 2] * w.z + y1[j + 3] * w.w;
        }
        att[t] = sigm(a);
    }

    // Reload src row (hot in L1/L2) and scatter-reduce
    float* op = out + dst * FF;
    #pragma unroll
    for (int t = 0; t < HH; t++) {
        float a = att[t];
        float4 m0 = sp[2 * t + 0];
        float4 m1 = sp[2 * t + 1];
        red4(op + t * 8,     a * m0.x, a * m0.y, a * m0.z, a * m0.w);
        red4(op + t * 8 + 4, a * m1.x, a * m1.y, a * m1.z, a * m1.w);
    }
}

// ---------------------------------------------------------------------------
extern "C" void kernel_launch(void* const* d_in, const int* in_sizes, int n_in,
                              void* d_out, int out_size)
{
    const float* h      = (const float*)d_in[0];
    const float* W_src  = (const float*)d_in[1];
    const float* b_src  = (const float*)d_in[2];
    const float* W_dst  = (const float*)d_in[3];
    const float* b_dst  = (const float*)d_in[4];
    const float* Wa1_s  = (const float*)d_in[5];
    const float* ba1_s  = (const float*)d_in[6];
    const float* Wa2_s  = (const float*)d_in[7];
    const float* ba2_s  = (const float*)d_in[8];
    const float* Wa1_d  = (const float*)d_in[9];
    const float* ba1_d  = (const float*)d_in[10];
    const float* Wa2_d  = (const float*)d_in[11];
    const float* ba2_d  = (const float*)d_in[12];
    const void*  eidx   = (const void*)d_in[13];
    float* out = (float*)d_out;

    node_kernel<<<(NN + 127) / 128, 128>>>(
        h, W_src, b_src, W_dst, b_dst,
        Wa1_d, ba1_d, Wa2_d, ba2_d,
        (const unsigned int*)eidx, out);

    edge_kernel<<<(EE + 127) / 128, 128>>>(
        eidx, Wa1_s, ba1_s, Wa2_s, ba2_s, out);
}

// round 5
// speedup vs baseline: 1.2384x; 1.2384x over previous
#include <cuda_runtime.h>

#define NN 100000
#define FF 64
#define HH 8
#define DD 8
#define EE 1200000
#define HID 32

// scratch (allocation-free rule: __device__ globals)
__device__ float g_src_buf[NN * FF];
__device__ float g_dst_buf[NN * FF];
__device__ int g_idx_is64;

__device__ __forceinline__ float leaky(float x) { return fmaxf(x, 0.2f * x); }
__device__ __forceinline__ float sigm(float x) { return 1.0f / (1.0f + __expf(-x)); }

__device__ __forceinline__ void red2(float* p, float x, float y) {
    asm volatile("red.global.add.v2.f32 [%0], {%1,%2};"
                 :: "l"(p), "f"(x), "f"(y) : "memory");
}

// ---------------------------------------------------------------------------
// Node kernel: g_src = h@W_src+b, g_dst = h@W_dst+b, out = sigmoid(mlp(g_dst))*g_dst
// Block 0 / thread 0 additionally probes edge_index dtype (int64 vs int32).
__global__ __launch_bounds__(128) void node_kernel(
    const float* __restrict__ h,
    const float* __restrict__ W_src, const float* __restrict__ b_src,
    const float* __restrict__ W_dst, const float* __restrict__ b_dst,
    const float* __restrict__ Wa1, const float* __restrict__ ba1,
    const float* __restrict__ Wa2, const float* __restrict__ ba2,
    const unsigned int* __restrict__ eidx_words,
    float* __restrict__ out)
{
    __shared__ float WsT[FF * FF];    // [j][k]
    __shared__ float WdT[FF * FF];
    __shared__ float W1T[HID * FF];   // [j][k]
    __shared__ float W2T[HH * HID];   // [t][j]
    __shared__ float bs[FF], bd[FF], b1[HID], b2[HH];

    int tid = threadIdx.x;
    if (blockIdx.x == 0 && tid == 0) {
        int is64 = 1;
        for (int i = 0; i < 8; i++)
            if (eidx_words[2 * i + 1] != 0u) is64 = 0;
        g_idx_is64 = is64;
    }
    for (int i = tid; i < FF * FF; i += 128) {
        int k = i >> 6, j = i & 63;
        WsT[j * FF + k] = W_src[i];
        WdT[j * FF + k] = W_dst[i];
    }
    for (int i = tid; i < HID * FF; i += 128) {
        int k = i / HID, j = i % HID;     // Wa1 is [F][HID]
        W1T[j * FF + k] = Wa1[i];
    }
    for (int i = tid; i < HH * HID; i += 128) {
        int k = i / HH, j = i % HH;       // Wa2 is [HID][H]
        W2T[j * HID + k] = Wa2[i];
    }
    if (tid < FF) { bs[tid] = b_src[tid]; bd[tid] = b_dst[tid]; }
    if (tid < HID) b1[tid] = ba1[tid];
    if (tid < HH)  b2[tid] = ba2[tid];
    __syncthreads();

    int node = blockIdx.x * 128 + tid;
    if (node >= NN) return;

    float hr[FF];
    {
        const float4* hp = (const float4*)(h + (size_t)node * FF);
        #pragma unroll
        for (int k4 = 0; k4 < FF / 4; k4++) {
            float4 v = hp[k4];
            hr[4 * k4 + 0] = v.x; hr[4 * k4 + 1] = v.y;
            hr[4 * k4 + 2] = v.z; hr[4 * k4 + 3] = v.w;
        }
    }

    // g_src -> gmem (not kept)
    {
        float4* gp = (float4*)(g_src_buf + (size_t)node * FF);
        #pragma unroll
        for (int j = 0; j < FF; j += 4) {
            float a0 = bs[j], a1 = bs[j + 1], a2 = bs[j + 2], a3 = bs[j + 3];
            #pragma unroll
            for (int k = 0; k < FF; k += 4) {
                float4 w0 = *(const float4*)&WsT[(j + 0) * FF + k];
                float4 w1 = *(const float4*)&WsT[(j + 1) * FF + k];
                float4 w2 = *(const float4*)&WsT[(j + 2) * FF + k];
                float4 w3 = *(const float4*)&WsT[(j + 3) * FF + k];
                a0 += hr[k] * w0.x + hr[k + 1] * w0.y + hr[k + 2] * w0.z + hr[k + 3] * w0.w;
                a1 += hr[k] * w1.x + hr[k + 1] * w1.y + hr[k + 2] * w1.z + hr[k + 3] * w1.w;
                a2 += hr[k] * w2.x + hr[k + 1] * w2.y + hr[k + 2] * w2.z + hr[k + 3] * w2.w;
                a3 += hr[k] * w3.x + hr[k + 1] * w3.y + hr[k + 2] * w3.z + hr[k + 3] * w3.w;
            }
            gp[j >> 2] = make_float4(a0, a1, a2, a3);
        }
    }

    // g_dst -> regs + gmem
    float gd[FF];
    {
        float4* gp = (float4*)(g_dst_buf + (size_t)node * FF);
        #pragma unroll
        for (int j = 0; j < FF; j += 4) {
            float a0 = bd[j], a1 = bd[j + 1], a2 = bd[j + 2], a3 = bd[j + 3];
            #pragma unroll
            for (int k = 0; k < FF; k += 4) {
                float4 w0 = *(const float4*)&WdT[(j + 0) * FF + k];
                float4 w1 = *(const float4*)&WdT[(j + 1) * FF + k];
                float4 w2 = *(const float4*)&WdT[(j + 2) * FF + k];
                float4 w3 = *(const float4*)&WdT[(j + 3) * FF + k];
                a0 += hr[k] * w0.x + hr[k + 1] * w0.y + hr[k + 2] * w0.z + hr[k + 3] * w0.w;
                a1 += hr[k] * w1.x + hr[k + 1] * w1.y + hr[k + 2] * w1.z + hr[k + 3] * w1.w;
                a2 += hr[k] * w2.x + hr[k + 1] * w2.y + hr[k + 2] * w2.z + hr[k + 3] * w2.w;
                a3 += hr[k] * w3.x + hr[k + 1] * w3.y + hr[k + 2] * w3.z + hr[k + 3] * w3.w;
            }
            gd[j + 0] = a0; gd[j + 1] = a1; gd[j + 2] = a2; gd[j + 3] = a3;
            gp[j >> 2] = make_float4(a0, a1, a2, a3);
        }
    }

    // attention MLP on g_dst (reuse hr registers for leaky(g_dst))
    #pragma unroll
    for (int k = 0; k < FF; k++) hr[k] = leaky(gd[k]);

    float y1[HID];
    #pragma unroll
    for (int j = 0; j < HID; j += 4) {
        float a0 = b1[j], a1 = b1[j + 1], a2 = b1[j + 2], a3 = b1[j + 3];
        #pragma unroll
        for (int k = 0; k < FF; k += 4) {
            float4 w0 = *(const float4*)&W1T[(j + 0) * FF + k];
            float4 w1 = *(const float4*)&W1T[(j + 1) * FF + k];
            float4 w2 = *(const float4*)&W1T[(j + 2) * FF + k];
            float4 w3 = *(const float4*)&W1T[(j + 3) * FF + k];
            a0 += hr[k] * w0.x + hr[k + 1] * w0.y + hr[k + 2] * w0.z + hr[k + 3] * w0.w;
            a1 += hr[k] * w1.x + hr[k + 1] * w1.y + hr[k + 2] * w1.z + hr[k + 3] * w1.w;
            a2 += hr[k] * w2.x + hr[k + 1] * w2.y + hr[k + 2] * w2.z + hr[k + 3] * w2.w;
            a3 += hr[k] * w3.x + hr[k + 1] * w3.y + hr[k + 2] * w3.z + hr[k + 3] * w3.w;
        }
        y1[j + 0] = leaky(a0); y1[j + 1] = leaky(a1);
        y1[j + 2] = leaky(a2); y1[j + 3] = leaky(a3);
    }

    float att[HH];
    #pragma unroll
    for (int t = 0; t < HH; t++) {
        float a = b2[t];
        #pragma unroll
        for (int j = 0; j < HID; j += 4) {
            float4 w = *(const float4*)&W2T[t * HID + j];
            a += y1[j] * w.x + y1[j + 1] * w.y + y1[j + 2] * w.z + y1[j + 3] * w.w;
        }
        att[t] = sigm(a);
    }

    // out = a_dst * g_dst  (initializes output; edge kernel atomically adds)
    float4* op = (float4*)(out + (size_t)node * FF);
    #pragma unroll
    for (int t = 0; t < HH; t++) {
        float a = att[t];
        op[2 * t + 0] = make_float4(a * gd[t * 8 + 0], a * gd[t * 8 + 1],
                                    a * gd[t * 8 + 2], a * gd[t * 8 + 3]);
        op[2 * t + 1] = make_float4(a * gd[t * 8 + 4], a * gd[t * 8 + 5],
                                    a * gd[t * 8 + 6], a * gd[t * 8 + 7]);
    }
}

// ---------------------------------------------------------------------------
// Edge kernel, cooperative layout: each warp owns 32 edges.
// Phase 1: coalesced gather of src/dst rows (float2 per lane), stage
//          lm = leaky(src+dst) into conflict-free shared (row stride 68).
// Phase 2: lane t runs the MLP for edge t from staged lm; att -> shared.
// Phase 3: coalesced reload of src row (L1-hot) + red.global.add.v2 scatter.
// EE = 1,200,000 = 9375 blocks * 4 warps * 32 edges exactly -> no tail.
#define LMS 68                 // lm row stride in floats (17 float4s, conflict-free)
#define ATTS 9                 // att row stride (9 coprime 32 -> conflict-free)

__global__ __launch_bounds__(128) void edge_kernel(
    const void* __restrict__ edge_index,
    const float* __restrict__ Wa1, const float* __restrict__ ba1,
    const float* __restrict__ Wa2, const float* __restrict__ ba2,
    float* __restrict__ out)
{
    __shared__ float W1T[HID * FF];
    __shared__ float W2T[HH * HID];
    __shared__ float b1[HID], b2[HH];
    __shared__ __align__(16) float LM[4][32 * LMS];
    __shared__ float ATT[4][32 * ATTS];

    int tid = threadIdx.x;
    for (int i = tid; i < HID * FF; i += 128) {
        int k = i / HID, j = i % HID;     // Wa1_src is [F][HID]
        W1T[j * FF + k] = Wa1[i];
    }
    for (int i = tid; i < HH * HID; i += 128) {
        int k = i / HH, j = i % HH;       // Wa2_src is [HID][H]
        W2T[j * HID + k] = Wa2[i];
    }
    if (tid < HID) b1[tid] = ba1[tid];
    if (tid < HH)  b2[tid] = ba2[tid];
    __syncthreads();

    const int warp = tid >> 5;
    const int lane = tid & 31;
    const int ebase = (blockIdx.x * 4 + warp) * 32;

    // each lane holds the indices of edge (ebase + lane)
    int srcI, dstI;
    if (g_idx_is64) {
        const long long* ei = (const long long*)edge_index;
        srcI = (int)ei[ebase + lane];
        dstI = (int)ei[EE + ebase + lane];
    } else {
        const int* ei = (const int*)edge_index;
        srcI = ei[ebase + lane];
        dstI = ei[EE + ebase + lane];
    }

    float* lmW = &LM[warp][0];

    // ---- Phase 1: cooperative gather + stage leaky(msg) ----
    #pragma unroll
    for (int e = 0; e < 32; e++) {
        int s = __shfl_sync(0xffffffffu, srcI, e);
        int d = __shfl_sync(0xffffffffu, dstI, e);
        float2 sv = *(const float2*)(g_src_buf + (size_t)s * FF + 2 * lane);
        float2 dv = *(const float2*)(g_dst_buf + (size_t)d * FF + 2 * lane);
        *(float2*)(lmW + e * LMS + 2 * lane) =
            make_float2(leaky(sv.x + dv.x), leaky(sv.y + dv.y));
    }
    __syncwarp();

    // ---- Phase 2: per-lane MLP on its own edge ----
    {
        float lm[FF];
        const float4* lp = (const float4*)(lmW + lane * LMS);
        #pragma unroll
        for (int k4 = 0; k4 < FF / 4; k4++) {
            float4 v = lp[k4];
            lm[4 * k4 + 0] = v.x; lm[4 * k4 + 1] = v.y;
            lm[4 * k4 + 2] = v.z; lm[4 * k4 + 3] = v.w;
        }

        float y1[HID];
        #pragma unroll
        for (int j = 0; j < HID; j += 4) {
            float a0 = b1[j], a1 = b1[j + 1], a2 = b1[j + 2], a3 = b1[j + 3];
            #pragma unroll
            for (int k = 0; k < FF; k += 4) {
                float4 w0 = *(const float4*)&W1T[(j + 0) * FF + k];
                float4 w1 = *(const float4*)&W1T[(j + 1) * FF + k];
                float4 w2 = *(const float4*)&W1T[(j + 2) * FF + k];
                float4 w3 = *(const float4*)&W1T[(j + 3) * FF + k];
                a0 += lm[k] * w0.x + lm[k + 1] * w0.y + lm[k + 2] * w0.z + lm[k + 3] * w0.w;
                a1 += lm[k] * w1.x + lm[k + 1] * w1.y + lm[k + 2] * w1.z + lm[k + 3] * w1.w;
                a2 += lm[k] * w2.x + lm[k + 1] * w2.y + lm[k + 2] * w2.z + lm[k + 3] * w2.w;
                a3 += lm[k] * w3.x + lm[k + 1] * w3.y + lm[k + 2] * w3.z + lm[k + 3] * w3.w;
            }
            y1[j + 0] = leaky(a0); y1[j + 1] = leaky(a1);
            y1[j + 2] = leaky(a2); y1[j + 3] = leaky(a3);
        }

        #pragma unroll
        for (int t = 0; t < HH; t++) {
            float a = b2[t];
            #pragma unroll
            for (int j = 0; j < HID; j += 4) {
                float4 w = *(const float4*)&W2T[t * HID + j];
                a += y1[j] * w.x + y1[j + 1] * w.y + y1[j + 2] * w.z + y1[j + 3] * w.w;
            }
            ATT[warp][lane * ATTS + t] = sigm(a);
        }
    }
    __syncwarp();

    // ---- Phase 3: cooperative scatter (coalesced red.v2 over dst row) ----
    const int myh = lane >> 2;   // head index for floats [2*lane, 2*lane+1]
    #pragma unroll
    for (int e = 0; e < 32; e++) {
        int s = __shfl_sync(0xffffffffu, srcI, e);
        int d = __shfl_sync(0xffffffffu, dstI, e);
        float av = ATT[warp][e * ATTS + myh];
        float2 sv = *(const float2*)(g_src_buf + (size_t)s * FF + 2 * lane);
        red2(out + (size_t)d * FF + 2 * lane, av * sv.x, av * sv.y);
    }
}

// ---------------------------------------------------------------------------
extern "C" void kernel_launch(void* const* d_in, const int* in_sizes, int n_in,
                              void* d_out, int out_size)
{
    const float* h      = (const float*)d_in[0];
    const float* W_src  = (const float*)d_in[1];
    const float* b_src  = (const float*)d_in[2];
    const float* W_dst  = (const float*)d_in[3];
    const float* b_dst  = (const float*)d_in[4];
    const float* Wa1_s  = (const float*)d_in[5];
    const float* ba1_s  = (const float*)d_in[6];
    const float* Wa2_s  = (const float*)d_in[7];
    const float* ba2_s  = (const float*)d_in[8];
    const float* Wa1_d  = (const float*)d_in[9];
    const float* ba1_d  = (const float*)d_in[10];
    const float* Wa2_d  = (const float*)d_in[11];
    const float* ba2_d  = (const float*)d_in[12];
    const void*  eidx   = (const void*)d_in[13];
    float* out = (float*)d_out;

    node_kernel<<<(NN + 127) / 128, 128>>>(
        h, W_src, b_src, W_dst, b_dst,
        Wa1_d, ba1_d, Wa2_d, ba2_d,
        (const unsigned int*)eidx, out);

    edge_kernel<<<EE / (4 * 32), 128>>>(
        eidx, Wa1_s, ba1_s, Wa2_s, ba2_s, out);
}

// round 6
// speedup vs baseline: 1.7150x; 1.3848x over previous
#include <cuda_runtime.h>
#include <cuda_bf16.h>

#define NN 100000
#define FF 64
#define HH 8
#define DD 8
#define EE 1200000
#define HID 32

// scratch (allocation-free rule: __device__ globals)
__device__ float g_src_buf[NN * FF];
__device__ float g_dst_buf[NN * FF];
__device__ int g_idx_is64;

__device__ __forceinline__ float leaky(float x) { return fmaxf(x, 0.2f * x); }
__device__ __forceinline__ float sigm(float x) { return 1.0f / (1.0f + __expf(-x)); }

__device__ __forceinline__ void red2(float* p, float x, float y) {
    asm volatile("red.global.add.v2.f32 [%0], {%1,%2};"
                 :: "l"(p), "f"(x), "f"(y) : "memory");
}

__device__ __forceinline__ unsigned pack_bf16(float lo, float hi) {
    __nv_bfloat162 t = __float22bfloat162_rn(make_float2(lo, hi));
    return *(unsigned*)&t;
}

// D += A@B, m16n8k16, bf16 in / fp32 accum
__device__ __forceinline__ void mma16816(float* d, const unsigned* a, const unsigned* b) {
    asm volatile(
        "mma.sync.aligned.m16n8k16.row.col.f32.bf16.bf16.f32 "
        "{%0,%1,%2,%3}, {%4,%5,%6,%7}, {%8,%9}, {%0,%1,%2,%3};"
        : "+f"(d[0]), "+f"(d[1]), "+f"(d[2]), "+f"(d[3])
        : "r"(a[0]), "r"(a[1]), "r"(a[2]), "r"(a[3]), "r"(b[0]), "r"(b[1]));
}

// ---------------------------------------------------------------------------
// Node kernel: g_src = h@W_src+b, g_dst = h@W_dst+b, out = sigmoid(mlp(g_dst))*g_dst
// Block 0 / thread 0 additionally probes edge_index dtype (int64 vs int32).
__global__ __launch_bounds__(128) void node_kernel(
    const float* __restrict__ h,
    const float* __restrict__ W_src, const float* __restrict__ b_src,
    const float* __restrict__ W_dst, const float* __restrict__ b_dst,
    const float* __restrict__ Wa1, const float* __restrict__ ba1,
    const float* __restrict__ Wa2, const float* __restrict__ ba2,
    const unsigned int* __restrict__ eidx_words,
    float* __restrict__ out)
{
    __shared__ float WsT[FF * FF];    // [j][k]
    __shared__ float WdT[FF * FF];
    __shared__ float W1T[HID * FF];   // [j][k]
    __shared__ float W2T[HH * HID];   // [t][j]
    __shared__ float bs[FF], bd[FF], b1[HID], b2[HH];

    int tid = threadIdx.x;
    if (blockIdx.x == 0 && tid == 0) {
        int is64 = 1;
        for (int i = 0; i < 8; i++)
            if (eidx_words[2 * i + 1] != 0u) is64 = 0;
        g_idx_is64 = is64;
    }
    for (int i = tid; i < FF * FF; i += 128) {
        int k = i >> 6, j = i & 63;
        WsT[j * FF + k] = W_src[i];
        WdT[j * FF + k] = W_dst[i];
    }
    for (int i = tid; i < HID * FF; i += 128) {
        int k = i / HID, j = i % HID;     // Wa1 is [F][HID]
        W1T[j * FF + k] = Wa1[i];
    }
    for (int i = tid; i < HH * HID; i += 128) {
        int k = i / HH, j = i % HH;       // Wa2 is [HID][H]
        W2T[j * HID + k] = Wa2[i];
    }
    if (tid < FF) { bs[tid] = b_src[tid]; bd[tid] = b_dst[tid]; }
    if (tid < HID) b1[tid] = ba1[tid];
    if (tid < HH)  b2[tid] = ba2[tid];
    __syncthreads();

    int node = blockIdx.x * 128 + tid;
    if (node >= NN) return;

    float hr[FF];
    {
        const float4* hp = (const float4*)(h + (size_t)node * FF);
        #pragma unroll
        for (int k4 = 0; k4 < FF / 4; k4++) {
            float4 v = hp[k4];
            hr[4 * k4 + 0] = v.x; hr[4 * k4 + 1] = v.y;
            hr[4 * k4 + 2] = v.z; hr[4 * k4 + 3] = v.w;
        }
    }

    // g_src -> gmem (not kept)
    {
        float4* gp = (float4*)(g_src_buf + (size_t)node * FF);
        #pragma unroll
        for (int j = 0; j < FF; j += 4) {
            float a0 = bs[j], a1 = bs[j + 1], a2 = bs[j + 2], a3 = bs[j + 3];
            #pragma unroll
            for (int k = 0; k < FF; k += 4) {
                float4 w0 = *(const float4*)&WsT[(j + 0) * FF + k];
                float4 w1 = *(const float4*)&WsT[(j + 1) * FF + k];
                float4 w2 = *(const float4*)&WsT[(j + 2) * FF + k];
                float4 w3 = *(const float4*)&WsT[(j + 3) * FF + k];
                a0 += hr[k] * w0.x + hr[k + 1] * w0.y + hr[k + 2] * w0.z + hr[k + 3] * w0.w;
                a1 += hr[k] * w1.x + hr[k + 1] * w1.y + hr[k + 2] * w1.z + hr[k + 3] * w1.w;
                a2 += hr[k] * w2.x + hr[k + 1] * w2.y + hr[k + 2] * w2.z + hr[k + 3] * w2.w;
                a3 += hr[k] * w3.x + hr[k + 1] * w3.y + hr[k + 2] * w3.z + hr[k + 3] * w3.w;
            }
            gp[j >> 2] = make_float4(a0, a1, a2, a3);
        }
    }

    // g_dst -> regs + gmem
    float gd[FF];
    {
        float4* gp = (float4*)(g_dst_buf + (size_t)node * FF);
        #pragma unroll
        for (int j = 0; j < FF; j += 4) {
            float a0 = bd[j], a1 = bd[j + 1], a2 = bd[j + 2], a3 = bd[j + 3];
            #pragma unroll
            for (int k = 0; k < FF; k += 4) {
                float4 w0 = *(const float4*)&WdT[(j + 0) * FF + k];
                float4 w1 = *(const float4*)&WdT[(j + 1) * FF + k];
                float4 w2 = *(const float4*)&WdT[(j + 2) * FF + k];
                float4 w3 = *(const float4*)&WdT[(j + 3) * FF + k];
                a0 += hr[k] * w0.x + hr[k + 1] * w0.y + hr[k + 2] * w0.z + hr[k + 3] * w0.w;
                a1 += hr[k] * w1.x + hr[k + 1] * w1.y + hr[k + 2] * w1.z + hr[k + 3] * w1.w;
                a2 += hr[k] * w2.x + hr[k + 1] * w2.y + hr[k + 2] * w2.z + hr[k + 3] * w2.w;
                a3 += hr[k] * w3.x + hr[k + 1] * w3.y + hr[k + 2] * w3.z + hr[k + 3] * w3.w;
            }
            gd[j + 0] = a0; gd[j + 1] = a1; gd[j + 2] = a2; gd[j + 3] = a3;
            gp[j >> 2] = make_float4(a0, a1, a2, a3);
        }
    }

    // attention MLP on g_dst (reuse hr registers for leaky(g_dst))
    #pragma unroll
    for (int k = 0; k < FF; k++) hr[k] = leaky(gd[k]);

    float y1[HID];
    #pragma unroll
    for (int j = 0; j < HID; j += 4) {
        float a0 = b1[j], a1 = b1[j + 1], a2 = b1[j + 2], a3 = b1[j + 3];
        #pragma unroll
        for (int k = 0; k < FF; k += 4) {
            float4 w0 = *(const float4*)&W1T[(j + 0) * FF + k];
            float4 w1 = *(const float4*)&W1T[(j + 1) * FF + k];
            float4 w2 = *(const float4*)&W1T[(j + 2) * FF + k];
            float4 w3 = *(const float4*)&W1T[(j + 3) * FF + k];
            a0 += hr[k] * w0.x + hr[k + 1] * w0.y + hr[k + 2] * w0.z + hr[k + 3] * w0.w;
            a1 += hr[k] * w1.x + hr[k + 1] * w1.y + hr[k + 2] * w1.z + hr[k + 3] * w1.w;
            a2 += hr[k] * w2.x + hr[k + 1] * w2.y + hr[k + 2] * w2.z + hr[k + 3] * w2.w;
            a3 += hr[k] * w3.x + hr[k + 1] * w3.y + hr[k + 2] * w3.z + hr[k + 3] * w3.w;
        }
        y1[j + 0] = leaky(a0); y1[j + 1] = leaky(a1);
        y1[j + 2] = leaky(a2); y1[j + 3] = leaky(a3);
    }

    float att[HH];
    #pragma unroll
    for (int t = 0; t < HH; t++) {
        float a = b2[t];
        #pragma unroll
        for (int j = 0; j < HID; j += 4) {
            float4 w = *(const float4*)&W2T[t * HID + j];
            a += y1[j] * w.x + y1[j + 1] * w.y + y1[j + 2] * w.z + y1[j + 3] * w.w;
        }
        att[t] = sigm(a);
    }

    // out = a_dst * g_dst  (initializes output; edge kernel atomically adds)
    float4* op = (float4*)(out + (size_t)node * FF);
    #pragma unroll
    for (int t = 0; t < HH; t++) {
        float a = att[t];
        op[2 * t + 0] = make_float4(a * gd[t * 8 + 0], a * gd[t * 8 + 1],
                                    a * gd[t * 8 + 2], a * gd[t * 8 + 3]);
        op[2 * t + 1] = make_float4(a * gd[t * 8 + 4], a * gd[t * 8 + 5],
                                    a * gd[t * 8 + 6], a * gd[t * 8 + 7]);
    }
}

// ---------------------------------------------------------------------------
// Edge kernel v3: tensor-core MLP.
// Each warp: 5 batches of 32 edges. Weights live as per-lane mma fragments
// (loaded once from global). Per batch:
//   P1: coalesced gather, lm = leaky(src+dst) staged as bf16 (stride 72 bf16)
//   P2: 2x m16-tiles: layer1 = 16x mma.m16n8k16 (bf16), bias+leaky in regs,
//       repack accum as A-frags, layer2 = 2x mma, sigmoid, att -> shared
//   P3: coalesced src reload + red.global.add.v2 scatter
// EE = 1,200,000 = 1875 blocks * 4 warps * 5 * 32 exactly.
#define LMW32 36               // lm row stride in uint32 (72 bf16), conflict-free
#define ATTS 10                // att row stride (float2-aligned)

__global__ __launch_bounds__(128) void edge_kernel(
    const void* __restrict__ edge_index,
    const float* __restrict__ Wa1, const float* __restrict__ ba1,
    const float* __restrict__ Wa2, const float* __restrict__ ba2,
    float* __restrict__ out)
{
    __shared__ unsigned LM[4][32 * LMW32];   // bf16x2 staging per warp
    __shared__ float ATT[4][32 * ATTS];

    const int tid  = threadIdx.x;
    const int warp = tid >> 5;
    const int lane = tid & 31;
    const int c = lane & 3;      // quad col
    const int r = lane >> 2;     // quad row

    // ---- weight fragments (register-resident, loaded once from global) ----
    // W1 [64,32] row-major = [k][n]; B-frag b0={W[k0][n],W[k0+1][n]}, b1={W[k0+8][n],W[k0+9][n]}
    unsigned w1f[4][4][2];
    #pragma unroll
    for (int ks = 0; ks < 4; ks++)
        #pragma unroll
        for (int nt = 0; nt < 4; nt++) {
            const float* base = Wa1 + (16 * ks + 2 * c) * HID + 8 * nt + r;
            w1f[ks][nt][0] = pack_bf16(base[0],        base[HID]);
            w1f[ks][nt][1] = pack_bf16(base[8 * HID],  base[9 * HID]);
        }
    // W2 [32,8] row-major
    unsigned w2f[2][2];
    #pragma unroll
    for (int ks = 0; ks < 2; ks++) {
        const float* base = Wa2 + (16 * ks + 2 * c) * HH + r;
        w2f[ks][0] = pack_bf16(base[0],      base[HH]);
        w2f[ks][1] = pack_bf16(base[8 * HH], base[9 * HH]);
    }
    // biases mapped to accumulator columns
    float bb0[4], bb1[4];
    #pragma unroll
    for (int nt = 0; nt < 4; nt++) {
        bb0[nt] = ba1[8 * nt + 2 * c];
        bb1[nt] = ba1[8 * nt + 2 * c + 1];
    }
    const float b2r0 = ba2[2 * c], b2r1 = ba2[2 * c + 1];

    unsigned* lmW = &LM[warp][0];
    float* attW = &ATT[warp][0];
    const int myh = lane >> 2;   // head for floats [2*lane, 2*lane+1]
    const int is64 = g_idx_is64;

    for (int b = 0; b < 5; b++) {
        const int ebase = (((blockIdx.x * 4 + warp) * 5) + b) * 32;

        int srcI, dstI;
        if (is64) {
            const long long* ei = (const long long*)edge_index;
            srcI = (int)ei[ebase + lane];
            dstI = (int)ei[EE + ebase + lane];
        } else {
            const int* ei = (const int*)edge_index;
            srcI = ei[ebase + lane];
            dstI = ei[EE + ebase + lane];
        }

        // ---- Phase 1: gather + stage leaky(msg) as bf16 ----
        #pragma unroll
        for (int e = 0; e < 32; e++) {
            int s = __shfl_sync(0xffffffffu, srcI, e);
            int d = __shfl_sync(0xffffffffu, dstI, e);
            float2 sv = *(const float2*)(g_src_buf + (size_t)s * FF + 2 * lane);
            float2 dv = *(const float2*)(g_dst_buf + (size_t)d * FF + 2 * lane);
            lmW[e * LMW32 + lane] = pack_bf16(leaky(sv.x + dv.x), leaky(sv.y + dv.y));
        }
        __syncwarp();

        // ---- Phase 2: tensor-core MLP (2 m-tiles of 16 edges) ----
        #pragma unroll
        for (int mt = 0; mt < 2; mt++) {
            float acc[4][4];
            #pragma unroll
            for (int nt = 0; nt < 4; nt++)
                acc[nt][0] = acc[nt][1] = acc[nt][2] = acc[nt][3] = 0.0f;

            #pragma unroll
            for (int ks = 0; ks < 4; ks++) {
                unsigned a[4];
                int base = (mt * 16 + r) * LMW32 + 8 * ks + c;
                a[0] = lmW[base];
                a[1] = lmW[base + 8 * LMW32];
                a[2] = lmW[base + 4];
                a[3] = lmW[base + 8 * LMW32 + 4];
                #pragma unroll
                for (int nt = 0; nt < 4; nt++)
                    mma16816(acc[nt], a, w1f[ks][nt]);
            }

            // bias + leaky, repack as layer-2 A fragments
            unsigned a2[2][4];
            #pragma unroll
            for (int nt = 0; nt < 4; nt++) {
                float v0 = leaky(acc[nt][0] + bb0[nt]);
                float v1 = leaky(acc[nt][1] + bb1[nt]);
                float v2 = leaky(acc[nt][2] + bb0[nt]);
                float v3 = leaky(acc[nt][3] + bb1[nt]);
                a2[nt >> 1][(nt & 1) * 2 + 0] = pack_bf16(v0, v1);
                a2[nt >> 1][(nt & 1) * 2 + 1] = pack_bf16(v2, v3);
            }

            float z[4] = {0.0f, 0.0f, 0.0f, 0.0f};
            mma16816(z, a2[0], w2f[0]);
            mma16816(z, a2[1], w2f[1]);

            *(float2*)&attW[(mt * 16 + r) * ATTS + 2 * c] =
                make_float2(sigm(z[0] + b2r0), sigm(z[1] + b2r1));
            *(float2*)&attW[(mt * 16 + r + 8) * ATTS + 2 * c] =
                make_float2(sigm(z[2] + b2r0), sigm(z[3] + b2r1));
        }
        __syncwarp();

        // ---- Phase 3: coalesced scatter ----
        #pragma unroll
        for (int e = 0; e < 32; e++) {
            int s = __shfl_sync(0xffffffffu, srcI, e);
            int d = __shfl_sync(0xffffffffu, dstI, e);
            float av = attW[e * ATTS + myh];
            float2 sv = *(const float2*)(g_src_buf + (size_t)s * FF + 2 * lane);
            red2(out + (size_t)d * FF + 2 * lane, av * sv.x, av * sv.y);
        }
        __syncwarp();
    }
}

// ---------------------------------------------------------------------------
extern "C" void kernel_launch(void* const* d_in, const int* in_sizes, int n_in,
                              void* d_out, int out_size)
{
    const float* h      = (const float*)d_in[0];
    const float* W_src  = (const float*)d_in[1];
    const float* b_src  = (const float*)d_in[2];
    const float* W_dst  = (const float*)d_in[3];
    const float* b_dst  = (const float*)d_in[4];
    const float* Wa1_s  = (const float*)d_in[5];
    const float* ba1_s  = (const float*)d_in[6];
    const float* Wa2_s  = (const float*)d_in[7];
    const float* ba2_s  = (const float*)d_in[8];
    const float* Wa1_d  = (const float*)d_in[9];
    const float* ba1_d  = (const float*)d_in[10];
    const float* Wa2_d  = (const float*)d_in[11];
    const float* ba2_d  = (const float*)d_in[12];
    const void*  eidx   = (const void*)d_in[13];
    float* out = (float*)d_out;

    node_kernel<<<(NN + 127) / 128, 128>>>(
        h, W_src, b_src, W_dst, b_dst,
        Wa1_d, ba1_d, Wa2_d, ba2_d,
        (const unsigned int*)eidx, out);

    edge_kernel<<<EE / (4 * 5 * 32), 128>>>(
        eidx, Wa1_s, ba1_s, Wa2_s, ba2_s, out);
}

// round 7
// speedup vs baseline: 2.1154x; 1.2334x over previous
#include <cuda_runtime.h>
#include <cuda_bf16.h>

#define NN 100000
#define FF 64
#define HH 8
#define DD 8
#define EE 1200000
#define HID 32

// scratch (allocation-free rule: __device__ globals)
__device__ float g_src_buf[NN * FF];
__device__ float g_dst_buf[NN * FF];
__device__ int g_idx_is64;

__device__ __forceinline__ float leaky(float x) { return fmaxf(x, 0.2f * x); }
__device__ __forceinline__ float sigm(float x) { return 1.0f / (1.0f + __expf(-x)); }

__device__ __forceinline__ void red2(float* p, float x, float y) {
    asm volatile("red.global.add.v2.f32 [%0], {%1,%2};"
                 :: "l"(p), "f"(x), "f"(y) : "memory");
}

__device__ __forceinline__ unsigned pack_bf16(float lo, float hi) {
    __nv_bfloat162 t = __float22bfloat162_rn(make_float2(lo, hi));
    return *(unsigned*)&t;
}

// D += A@B, m16n8k16, bf16 in / fp32 accum
__device__ __forceinline__ void mma16816(float* d, const unsigned* a, const unsigned* b) {
    asm volatile(
        "mma.sync.aligned.m16n8k16.row.col.f32.bf16.bf16.f32 "
        "{%0,%1,%2,%3}, {%4,%5,%6,%7}, {%8,%9}, {%0,%1,%2,%3};"
        : "+f"(d[0]), "+f"(d[1]), "+f"(d[2]), "+f"(d[3])
        : "r"(a[0]), "r"(a[1]), "r"(a[2]), "r"(a[3]), "r"(b[0]), "r"(b[1]));
}

#define LMW32 36               // staging row stride in uint32 (72 bf16), conflict-free
#define ATTS 10                // att row stride

// ---------------------------------------------------------------------------
// GEMM kernel: g_src = h@W_src+b_src, g_dst = h@W_dst+b_dst (both to gmem).
// Lean per-thread footprint (no MLP, no gd retention) -> no spills.
// Block 0 / thread 0 probes edge_index dtype (int64 vs int32).
__global__ __launch_bounds__(128) void gemm_kernel(
    const float* __restrict__ h,
    const float* __restrict__ W_src, const float* __restrict__ b_src,
    const float* __restrict__ W_dst, const float* __restrict__ b_dst,
    const unsigned int* __restrict__ eidx_words)
{
    __shared__ float WsT[FF * FF];    // [j][k]
    __shared__ float WdT[FF * FF];
    __shared__ float bs[FF], bd[FF];

    int tid = threadIdx.x;
    if (blockIdx.x == 0 && tid == 0) {
        int is64 = 1;
        for (int i = 0; i < 8; i++)
            if (eidx_words[2 * i + 1] != 0u) is64 = 0;
        g_idx_is64 = is64;
    }
    for (int i = tid; i < FF * FF; i += 128) {
        int k = i >> 6, j = i & 63;
        WsT[j * FF + k] = W_src[i];
        WdT[j * FF + k] = W_dst[i];
    }
    if (tid < FF) { bs[tid] = b_src[tid]; bd[tid] = b_dst[tid]; }
    __syncthreads();

    int node = blockIdx.x * 128 + tid;
    if (node >= NN) return;

    float hr[FF];
    {
        const float4* hp = (const float4*)(h + (size_t)node * FF);
        #pragma unroll
        for (int k4 = 0; k4 < FF / 4; k4++) {
            float4 v = hp[k4];
            hr[4 * k4 + 0] = v.x; hr[4 * k4 + 1] = v.y;
            hr[4 * k4 + 2] = v.z; hr[4 * k4 + 3] = v.w;
        }
    }

    float4* gps = (float4*)(g_src_buf + (size_t)node * FF);
    float4* gpd = (float4*)(g_dst_buf + (size_t)node * FF);
    #pragma unroll
    for (int j = 0; j < FF; j += 4) {
        float s0 = bs[j], s1 = bs[j + 1], s2 = bs[j + 2], s3 = bs[j + 3];
        float d0 = bd[j], d1 = bd[j + 1], d2 = bd[j + 2], d3 = bd[j + 3];
        #pragma unroll
        for (int k = 0; k < FF; k += 4) {
            float4 w0 = *(const float4*)&WsT[(j + 0) * FF + k];
            float4 w1 = *(const float4*)&WsT[(j + 1) * FF + k];
            float4 w2 = *(const float4*)&WsT[(j + 2) * FF + k];
            float4 w3 = *(const float4*)&WsT[(j + 3) * FF + k];
            s0 += hr[k] * w0.x + hr[k + 1] * w0.y + hr[k + 2] * w0.z + hr[k + 3] * w0.w;
            s1 += hr[k] * w1.x + hr[k + 1] * w1.y + hr[k + 2] * w1.z + hr[k + 3] * w1.w;
            s2 += hr[k] * w2.x + hr[k + 1] * w2.y + hr[k + 2] * w2.z + hr[k + 3] * w2.w;
            s3 += hr[k] * w3.x + hr[k + 1] * w3.y + hr[k + 2] * w3.z + hr[k + 3] * w3.w;
            float4 v0 = *(const float4*)&WdT[(j + 0) * FF + k];
            float4 v1 = *(const float4*)&WdT[(j + 1) * FF + k];
            float4 v2 = *(const float4*)&WdT[(j + 2) * FF + k];
            float4 v3 = *(const float4*)&WdT[(j + 3) * FF + k];
            d0 += hr[k] * v0.x + hr[k + 1] * v0.y + hr[k + 2] * v0.z + hr[k + 3] * v0.w;
            d1 += hr[k] * v1.x + hr[k + 1] * v1.y + hr[k + 2] * v1.z + hr[k + 3] * v1.w;
            d2 += hr[k] * v2.x + hr[k + 1] * v2.y + hr[k + 2] * v2.z + hr[k + 3] * v2.w;
            d3 += hr[k] * v3.x + hr[k + 1] * v3.y + hr[k + 2] * v3.z + hr[k + 3] * v3.w;
        }
        gps[j >> 2] = make_float4(s0, s1, s2, s3);
        gpd[j >> 2] = make_float4(d0, d1, d2, d3);
    }
}

// ---------------------------------------------------------------------------
// Node-attention kernel (tensor-core MLP, same machinery as edge kernel):
// att = sigmoid(mlp_dst(leaky(g_dst))); out[node] = att[h] * g_dst[node]
// Each warp handles 32 consecutive nodes. 3125 warp-batches -> grid 782.
__global__ __launch_bounds__(128) void natt_kernel(
    const float* __restrict__ Wa1, const float* __restrict__ ba1,
    const float* __restrict__ Wa2, const float* __restrict__ ba2,
    float* __restrict__ out)
{
    __shared__ unsigned LM[4][32 * LMW32];
    __shared__ float ATT[4][32 * ATTS];

    const int tid  = threadIdx.x;
    const int warp = tid >> 5;
    const int lane = tid & 31;
    const int c = lane & 3;
    const int r = lane >> 2;

    const int nbase = (blockIdx.x * 4 + warp) * 32;
    if (nbase >= NN) return;

    // weight fragments (register-resident)
    unsigned w1f[4][4][2];
    #pragma unroll
    for (int ks = 0; ks < 4; ks++)
        #pragma unroll
        for (int nt = 0; nt < 4; nt++) {
            const float* base = Wa1 + (16 * ks + 2 * c) * HID + 8 * nt + r;
            w1f[ks][nt][0] = pack_bf16(base[0],        base[HID]);
            w1f[ks][nt][1] = pack_bf16(base[8 * HID],  base[9 * HID]);
        }
    unsigned w2f[2][2];
    #pragma unroll
    for (int ks = 0; ks < 2; ks++) {
        const float* base = Wa2 + (16 * ks + 2 * c) * HH + r;
        w2f[ks][0] = pack_bf16(base[0],      base[HH]);
        w2f[ks][1] = pack_bf16(base[8 * HH], base[9 * HH]);
    }
    float bb0[4], bb1[4];
    #pragma unroll
    for (int nt = 0; nt < 4; nt++) {
        bb0[nt] = ba1[8 * nt + 2 * c];
        bb1[nt] = ba1[8 * nt + 2 * c + 1];
    }
    const float b2r0 = ba2[2 * c], b2r1 = ba2[2 * c + 1];

    unsigned* lmW = &LM[warp][0];
    float* attW = &ATT[warp][0];
    const int myh = lane >> 2;

    // P1: coalesced contiguous-row load + stage leaky(g_dst) as bf16
    #pragma unroll
    for (int e = 0; e < 32; e++) {
        float2 dv = *(const float2*)(g_dst_buf + (size_t)(nbase + e) * FF + 2 * lane);
        lmW[e * LMW32 + lane] = pack_bf16(leaky(dv.x), leaky(dv.y));
    }
    __syncwarp();

    // P2: tensor-core MLP
    #pragma unroll
    for (int mt = 0; mt < 2; mt++) {
        float acc[4][4];
        #pragma unroll
        for (int nt = 0; nt < 4; nt++)
            acc[nt][0] = acc[nt][1] = acc[nt][2] = acc[nt][3] = 0.0f;

        #pragma unroll
        for (int ks = 0; ks < 4; ks++) {
            unsigned a[4];
            int base = (mt * 16 + r) * LMW32 + 8 * ks + c;
            a[0] = lmW[base];
            a[1] = lmW[base + 8 * LMW32];
            a[2] = lmW[base + 4];
            a[3] = lmW[base + 8 * LMW32 + 4];
            #pragma unroll
            for (int nt = 0; nt < 4; nt++)
                mma16816(acc[nt], a, w1f[ks][nt]);
        }

        unsigned a2[2][4];
        #pragma unroll
        for (int nt = 0; nt < 4; nt++) {
            float v0 = leaky(acc[nt][0] + bb0[nt]);
            float v1 = leaky(acc[nt][1] + bb1[nt]);
            float v2 = leaky(acc[nt][2] + bb0[nt]);
            float v3 = leaky(acc[nt][3] + bb1[nt]);
            a2[nt >> 1][(nt & 1) * 2 + 0] = pack_bf16(v0, v1);
            a2[nt >> 1][(nt & 1) * 2 + 1] = pack_bf16(v2, v3);
        }

        float z[4] = {0.0f, 0.0f, 0.0f, 0.0f};
        mma16816(z, a2[0], w2f[0]);
        mma16816(z, a2[1], w2f[1]);

        *(float2*)&attW[(mt * 16 + r) * ATTS + 2 * c] =
            make_float2(sigm(z[0] + b2r0), sigm(z[1] + b2r1));
        *(float2*)&attW[(mt * 16 + r + 8) * ATTS + 2 * c] =
            make_float2(sigm(z[2] + b2r0), sigm(z[3] + b2r1));
    }
    __syncwarp();

    // P3: out = att * g_dst (plain coalesced store; initializes out)
    #pragma unroll
    for (int e = 0; e < 32; e++) {
        float av = attW[e * ATTS + myh];
        float2 dv = *(const float2*)(g_dst_buf + (size_t)(nbase + e) * FF + 2 * lane);
        *(float2*)(out + (size_t)(nbase + e) * FF + 2 * lane) =
            make_float2(av * dv.x, av * dv.y);
    }
}

// ---------------------------------------------------------------------------
// Edge kernel (unchanged from round 5): tensor-core MLP, 5 batches of 32
// edges per warp. EE = 1875 blocks * 4 warps * 5 * 32 exactly.
__global__ __launch_bounds__(128) void edge_kernel(
    const void* __restrict__ edge_index,
    const float* __restrict__ Wa1, const float* __restrict__ ba1,
    const float* __restrict__ Wa2, const float* __restrict__ ba2,
    float* __restrict__ out)
{
    __shared__ unsigned LM[4][32 * LMW32];
    __shared__ float ATT[4][32 * ATTS];

    const int tid  = threadIdx.x;
    const int warp = tid >> 5;
    const int lane = tid & 31;
    const int c = lane & 3;
    const int r = lane >> 2;

    unsigned w1f[4][4][2];
    #pragma unroll
    for (int ks = 0; ks < 4; ks++)
        #pragma unroll
        for (int nt = 0; nt < 4; nt++) {
            const float* base = Wa1 + (16 * ks + 2 * c) * HID + 8 * nt + r;
            w1f[ks][nt][0] = pack_bf16(base[0],        base[HID]);
            w1f[ks][nt][1] = pack_bf16(base[8 * HID],  base[9 * HID]);
        }
    unsigned w2f[2][2];
    #pragma unroll
    for (int ks = 0; ks < 2; ks++) {
        const float* base = Wa2 + (16 * ks + 2 * c) * HH + r;
        w2f[ks][0] = pack_bf16(base[0],      base[HH]);
        w2f[ks][1] = pack_bf16(base[8 * HH], base[9 * HH]);
    }
    float bb0[4], bb1[4];
    #pragma unroll
    for (int nt = 0; nt < 4; nt++) {
        bb0[nt] = ba1[8 * nt + 2 * c];
        bb1[nt] = ba1[8 * nt + 2 * c + 1];
    }
    const float b2r0 = ba2[2 * c], b2r1 = ba2[2 * c + 1];

    unsigned* lmW = &LM[warp][0];
    float* attW = &ATT[warp][0];
    const int myh = lane >> 2;
    const int is64 = g_idx_is64;

    for (int b = 0; b < 5; b++) {
        const int ebase = (((blockIdx.x * 4 + warp) * 5) + b) * 32;

        int srcI, dstI;
        if (is64) {
            const long long* ei = (const long long*)edge_index;
            srcI = (int)ei[ebase + lane];
            dstI = (int)ei[EE + ebase + lane];
        } else {
            const int* ei = (const int*)edge_index;
            srcI = ei[ebase + lane];
            dstI = ei[EE + ebase + lane];
        }

        #pragma unroll
        for (int e = 0; e < 32; e++) {
            int s = __shfl_sync(0xffffffffu, srcI, e);
            int d = __shfl_sync(0xffffffffu, dstI, e);
            float2 sv = *(const float2*)(g_src_buf + (size_t)s * FF + 2 * lane);
            float2 dv = *(const float2*)(g_dst_buf + (size_t)d * FF + 2 * lane);
            lmW[e * LMW32 + lane] = pack_bf16(leaky(sv.x + dv.x), leaky(sv.y + dv.y));
        }
        __syncwarp();

        #pragma unroll
        for (int mt = 0; mt < 2; mt++) {
            float acc[4][4];
            #pragma unroll
            for (int nt = 0; nt < 4; nt++)
                acc[nt][0] = acc[nt][1] = acc[nt][2] = acc[nt][3] = 0.0f;

            #pragma unroll
            for (int ks = 0; ks < 4; ks++) {
                unsigned a[4];
                int base = (mt * 16 + r) * LMW32 + 8 * ks + c;
                a[0] = lmW[base];
                a[1] = lmW[base + 8 * LMW32];
                a[2] = lmW[base + 4];
                a[3] = lmW[base + 8 * LMW32 + 4];
                #pragma unroll
                for (int nt = 0; nt < 4; nt++)
                    mma16816(acc[nt], a, w1f[ks][nt]);
            }

            unsigned a2[2][4];
            #pragma unroll
            for (int nt = 0; nt < 4; nt++) {
                float v0 = leaky(acc[nt][0] + bb0[nt]);
                float v1 = leaky(acc[nt][1] + bb1[nt]);
                float v2 = leaky(acc[nt][2] + bb0[nt]);
                float v3 = leaky(acc[nt][3] + bb1[nt]);
                a2[nt >> 1][(nt & 1) * 2 + 0] = pack_bf16(v0, v1);
                a2[nt >> 1][(nt & 1) * 2 + 1] = pack_bf16(v2, v3);
            }

            float z[4] = {0.0f, 0.0f, 0.0f, 0.0f};
            mma16816(z, a2[0], w2f[0]);
            mma16816(z, a2[1], w2f[1]);

            *(float2*)&attW[(mt * 16 + r) * ATTS + 2 * c] =
                make_float2(sigm(z[0] + b2r0), sigm(z[1] + b2r1));
            *(float2*)&attW[(mt * 16 + r + 8) * ATTS + 2 * c] =
                make_float2(sigm(z[2] + b2r0), sigm(z[3] + b2r1));
        }
        __syncwarp();

        #pragma unroll
        for (int e = 0; e < 32; e++) {
            int s = __shfl_sync(0xffffffffu, srcI, e);
            int d = __shfl_sync(0xffffffffu, dstI, e);
            float av = attW[e * ATTS + myh];
            float2 sv = *(const float2*)(g_src_buf + (size_t)s * FF + 2 * lane);
            red2(out + (size_t)d * FF + 2 * lane, av * sv.x, av * sv.y);
        }
        __syncwarp();
    }
}

// ---------------------------------------------------------------------------
extern "C" void kernel_launch(void* const* d_in, const int* in_sizes, int n_in,
                              void* d_out, int out_size)
{
    const float* h      = (const float*)d_in[0];
    const float* W_src  = (const float*)d_in[1];
    const float* b_src  = (const float*)d_in[2];
    const float* W_dst  = (const float*)d_in[3];
    const float* b_dst  = (const float*)d_in[4];
    const float* Wa1_s  = (const float*)d_in[5];
    const float* ba1_s  = (const float*)d_in[6];
    const float* Wa2_s  = (const float*)d_in[7];
    const float* ba2_s  = (const float*)d_in[8];
    const float* Wa1_d  = (const float*)d_in[9];
    const float* ba1_d  = (const float*)d_in[10];
    const float* Wa2_d  = (const float*)d_in[11];
    const float* ba2_d  = (const float*)d_in[12];
    const void*  eidx   = (const void*)d_in[13];
    float* out = (float*)d_out;

    gemm_kernel<<<(NN + 127) / 128, 128>>>(
        h, W_src, b_src, W_dst, b_dst, (const unsigned int*)eidx);

    natt_kernel<<<(NN / 32 + 3) / 4, 128>>>(
        Wa1_d, ba1_d, Wa2_d, ba2_d, out);

    edge_kernel<<<EE / (4 * 5 * 32), 128>>>(
        eidx, Wa1_s, ba1_s, Wa2_s, ba2_s, out);
}

// round 8
// speedup vs baseline: 3.3122x; 1.5658x over previous
#include <cuda_runtime.h>
#include <cuda_bf16.h>

#define NN 100000
#define FF 64
#define HH 8
#define DD 8
#define EE 1200000
#define HID 32

// scratch (allocation-free rule: __device__ globals)
__device__ float g_src_buf[NN * FF];
__device__ float g_dst_buf[NN * FF];
__device__ int g_idx_is64;

__device__ __forceinline__ float leaky(float x) { return fmaxf(x, 0.2f * x); }
__device__ __forceinline__ float sigm(float x) { return 1.0f / (1.0f + __expf(-x)); }

__device__ __forceinline__ void red2(float* p, float x, float y) {
    asm volatile("red.global.add.v2.f32 [%0], {%1,%2};"
                 :: "l"(p), "f"(x), "f"(y) : "memory");
}

__device__ __forceinline__ unsigned pack_bf16(float lo, float hi) {
    __nv_bfloat162 t = __float22bfloat162_rn(make_float2(lo, hi));
    return *(unsigned*)&t;
}

// split x into bf16 hi + bf16 lo (residual)
__device__ __forceinline__ void split_pack(float a, float b, unsigned& hi, unsigned& lo) {
    __nv_bfloat16 ah = __float2bfloat16(a), bh = __float2bfloat16(b);
    float ar = a - __bfloat162float(ah);
    float br = b - __bfloat162float(bh);
    __nv_bfloat162 t; t.x = ah; t.y = bh;
    hi = *(unsigned*)&t;
    lo = pack_bf16(ar, br);
}

// D += A@B, m16n8k16, bf16 in / fp32 accum
__device__ __forceinline__ void mma16816(float* d, const unsigned* a, const unsigned* b) {
    asm volatile(
        "mma.sync.aligned.m16n8k16.row.col.f32.bf16.bf16.f32 "
        "{%0,%1,%2,%3}, {%4,%5,%6,%7}, {%8,%9}, {%0,%1,%2,%3};"
        : "+f"(d[0]), "+f"(d[1]), "+f"(d[2]), "+f"(d[3])
        : "r"(a[0]), "r"(a[1]), "r"(a[2]), "r"(a[3]), "r"(b[0]), "r"(b[1]));
}

#define LMW32 36               // staging row stride in uint32 (72 bf16), conflict-free
#define ATTS 10                // att row stride

// ---------------------------------------------------------------------------
// Fused node kernel: tensor-core GEMM (hi/lo-split bf16) + node attention.
// Block = 128 threads = 4 warps, owns 128 consecutive nodes.
//   warps 0,1: g_src cols [0,32)/[32,64);  warps 2,3: g_dst same.
// Phase A: stage h as bf16 hi/lo; 3-way split MMAs; g -> gmem (+bias).
// Phase B (after syncthreads): node-attention MLP on g_dst (reload L1-hot),
//   out[node] = sigmoid(mlp_dst(leaky(g_dst))) * g_dst.
__global__ __launch_bounds__(128) void node_kernel(
    const float* __restrict__ h,
    const float* __restrict__ W_src, const float* __restrict__ b_src,
    const float* __restrict__ W_dst, const float* __restrict__ b_dst,
    const float* __restrict__ Wa1, const float* __restrict__ ba1,
    const float* __restrict__ Wa2, const float* __restrict__ ba2,
    const unsigned int* __restrict__ eidx_words,
    float* __restrict__ out)
{
    __shared__ unsigned AHI[128 * LMW32];   // 18KB, reused as natt LM staging
    __shared__ unsigned ALO[128 * LMW32];   // 18KB
    __shared__ float ATT[4][32 * ATTS];

    const int tid  = threadIdx.x;
    const int warp = tid >> 5;
    const int lane = tid & 31;
    const int c = lane & 3;
    const int r = lane >> 2;
    const int blockbase = blockIdx.x * 128;

    if (blockIdx.x == 0 && tid == 0) {
        int is64 = 1;
        for (int i = 0; i < 8; i++)
            if (eidx_words[2 * i + 1] != 0u) is64 = 0;
        g_idx_is64 = is64;
    }

    // ---- GEMM weight fragments (hi/lo), this warp's matrix + column half ----
    const int mat = warp >> 1;                 // 0 = src, 1 = dst
    const int colbase = 32 * (warp & 1);
    const float* Wm = mat ? W_dst : W_src;     // [k][n] row-major
    const float* bm = mat ? b_dst : b_src;

    unsigned bhi[4][4][2], blo[4][4][2];
    #pragma unroll
    for (int ks = 0; ks < 4; ks++)
        #pragma unroll
        for (int nt = 0; nt < 4; nt++) {
            const float* base = Wm + (16 * ks + 2 * c) * FF + colbase + 8 * nt + r;
            split_pack(base[0],       base[FF],     bhi[ks][nt][0], blo[ks][nt][0]);
            split_pack(base[8 * FF],  base[9 * FF], bhi[ks][nt][1], blo[ks][nt][1]);
        }
    float gb0[4], gb1[4];
    #pragma unroll
    for (int nt = 0; nt < 4; nt++) {
        gb0[nt] = bm[colbase + 8 * nt + 2 * c];
        gb1[nt] = bm[colbase + 8 * nt + 2 * c + 1];
    }

    // ---- natt (dst-MLP) weight fragments, all warps ----
    unsigned w1f[4][4][2];
    #pragma unroll
    for (int ks = 0; ks < 4; ks++)
        #pragma unroll
        for (int nt = 0; nt < 4; nt++) {
            const float* base = Wa1 + (16 * ks + 2 * c) * HID + 8 * nt + r;
            w1f[ks][nt][0] = pack_bf16(base[0],        base[HID]);
            w1f[ks][nt][1] = pack_bf16(base[8 * HID],  base[9 * HID]);
        }
    unsigned w2f[2][2];
    #pragma unroll
    for (int ks = 0; ks < 2; ks++) {
        const float* base = Wa2 + (16 * ks + 2 * c) * HH + r;
        w2f[ks][0] = pack_bf16(base[0],      base[HH]);
        w2f[ks][1] = pack_bf16(base[8 * HH], base[9 * HH]);
    }
    float bb0[4], bb1[4];
    #pragma unroll
    for (int nt = 0; nt < 4; nt++) {
        bb0[nt] = ba1[8 * nt + 2 * c];
        bb1[nt] = ba1[8 * nt + 2 * c + 1];
    }
    const float b2r0 = ba2[2 * c], b2r1 = ba2[2 * c + 1];

    // ---- Phase A1: stage h as hi/lo bf16 (warp w -> rows [32w, 32w+32)) ----
    #pragma unroll
    for (int e = 0; e < 32; e++) {
        int row = blockbase + 32 * warp + e;
        float2 v = (row < NN) ? *(const float2*)(h + (size_t)row * FF + 2 * lane)
                              : make_float2(0.0f, 0.0f);
        unsigned hv, lv;
        split_pack(v.x, v.y, hv, lv);
        AHI[(32 * warp + e) * LMW32 + lane] = hv;
        ALO[(32 * warp + e) * LMW32 + lane] = lv;
    }
    __syncthreads();

    // ---- Phase A2: MMAs over 8 m-tiles ----
    float* gout = mat ? g_dst_buf : g_src_buf;
    #pragma unroll
    for (int mt = 0; mt < 8; mt++) {
        float acc[4][4];
        #pragma unroll
        for (int nt = 0; nt < 4; nt++)
            acc[nt][0] = acc[nt][1] = acc[nt][2] = acc[nt][3] = 0.0f;

        #pragma unroll
        for (int ks = 0; ks < 4; ks++) {
            int base = (mt * 16 + r) * LMW32 + 8 * ks + c;
            unsigned ah[4], al[4];
            ah[0] = AHI[base];               al[0] = ALO[base];
            ah[1] = AHI[base + 8 * LMW32];   al[1] = ALO[base + 8 * LMW32];
            ah[2] = AHI[base + 4];           al[2] = ALO[base + 4];
            ah[3] = AHI[base + 8 * LMW32 + 4]; al[3] = ALO[base + 8 * LMW32 + 4];
            #pragma unroll
            for (int nt = 0; nt < 4; nt++) {
                mma16816(acc[nt], ah, blo[ks][nt]);
                mma16816(acc[nt], al, bhi[ks][nt]);
                mma16816(acc[nt], ah, bhi[ks][nt]);
            }
        }

        int row0 = blockbase + 16 * mt + r;
        int row8 = row0 + 8;
        #pragma unroll
        for (int nt = 0; nt < 4; nt++) {
            int col = colbase + 8 * nt + 2 * c;
            if (row0 < NN)
                *(float2*)(gout + (size_t)row0 * FF + col) =
                    make_float2(acc[nt][0] + gb0[nt], acc[nt][1] + gb1[nt]);
            if (row8 < NN)
                *(float2*)(gout + (size_t)row8 * FF + col) =
                    make_float2(acc[nt][2] + gb0[nt], acc[nt][3] + gb1[nt]);
        }
    }
    __syncthreads();   // g_dst stores visible; AHI free for reuse

    // ---- Phase B: node attention (warp w -> nodes [nbase, nbase+32)) ----
    const int nbase = blockbase + 32 * warp;
    if (nbase >= NN) return;

    unsigned* lmW = &AHI[(32 * warp) * LMW32];
    float* attW = &ATT[warp][0];
    const int myh = lane >> 2;

    #pragma unroll
    for (int e = 0; e < 32; e++) {
        float2 dv = *(const float2*)(g_dst_buf + (size_t)(nbase + e) * FF + 2 * lane);
        lmW[e * LMW32 + lane] = pack_bf16(leaky(dv.x), leaky(dv.y));
    }
    __syncwarp();

    #pragma unroll
    for (int mt = 0; mt < 2; mt++) {
        float acc[4][4];
        #pragma unroll
        for (int nt = 0; nt < 4; nt++)
            acc[nt][0] = acc[nt][1] = acc[nt][2] = acc[nt][3] = 0.0f;

        #pragma unroll
        for (int ks = 0; ks < 4; ks++) {
            unsigned a[4];
            int base = (mt * 16 + r) * LMW32 + 8 * ks + c;
            a[0] = lmW[base];
            a[1] = lmW[base + 8 * LMW32];
            a[2] = lmW[base + 4];
            a[3] = lmW[base + 8 * LMW32 + 4];
            #pragma unroll
            for (int nt = 0; nt < 4; nt++)
                mma16816(acc[nt], a, w1f[ks][nt]);
        }

        unsigned a2[2][4];
        #pragma unroll
        for (int nt = 0; nt < 4; nt++) {
            float v0 = leaky(acc[nt][0] + bb0[nt]);
            float v1 = leaky(acc[nt][1] + bb1[nt]);
            float v2 = leaky(acc[nt][2] + bb0[nt]);
            float v3 = leaky(acc[nt][3] + bb1[nt]);
            a2[nt >> 1][(nt & 1) * 2 + 0] = pack_bf16(v0, v1);
            a2[nt >> 1][(nt & 1) * 2 + 1] = pack_bf16(v2, v3);
        }

        float z[4] = {0.0f, 0.0f, 0.0f, 0.0f};
        mma16816(z, a2[0], w2f[0]);
        mma16816(z, a2[1], w2f[1]);

        *(float2*)&attW[(mt * 16 + r) * ATTS + 2 * c] =
            make_float2(sigm(z[0] + b2r0), sigm(z[1] + b2r1));
        *(float2*)&attW[(mt * 16 + r + 8) * ATTS + 2 * c] =
            make_float2(sigm(z[2] + b2r0), sigm(z[3] + b2r1));
    }
    __syncwarp();

    #pragma unroll
    for (int e = 0; e < 32; e++) {
        float av = attW[e * ATTS + myh];
        float2 dv = *(const float2*)(g_dst_buf + (size_t)(nbase + e) * FF + 2 * lane);
        *(float2*)(out + (size_t)(nbase + e) * FF + 2 * lane) =
            make_float2(av * dv.x, av * dv.y);
    }
}

// ---------------------------------------------------------------------------
// Edge kernel (unchanged, known-good): tensor-core MLP, 5 batches of 32
// edges per warp. EE = 1875 blocks * 4 warps * 5 * 32 exactly.
__global__ __launch_bounds__(128) void edge_kernel(
    const void* __restrict__ edge_index,
    const float* __restrict__ Wa1, const float* __restrict__ ba1,
    const float* __restrict__ Wa2, const float* __restrict__ ba2,
    float* __restrict__ out)
{
    __shared__ unsigned LM[4][32 * LMW32];
    __shared__ float ATT[4][32 * ATTS];

    const int tid  = threadIdx.x;
    const int warp = tid >> 5;
    const int lane = tid & 31;
    const int c = lane & 3;
    const int r = lane >> 2;

    unsigned w1f[4][4][2];
    #pragma unroll
    for (int ks = 0; ks < 4; ks++)
        #pragma unroll
        for (int nt = 0; nt < 4; nt++) {
            const float* base = Wa1 + (16 * ks + 2 * c) * HID + 8 * nt + r;
            w1f[ks][nt][0] = pack_bf16(base[0],        base[HID]);
            w1f[ks][nt][1] = pack_bf16(base[8 * HID],  base[9 * HID]);
        }
    unsigned w2f[2][2];
    #pragma unroll
    for (int ks = 0; ks < 2; ks++) {
        const float* base = Wa2 + (16 * ks + 2 * c) * HH + r;
        w2f[ks][0] = pack_bf16(base[0],      base[HH]);
        w2f[ks][1] = pack_bf16(base[8 * HH], base[9 * HH]);
    }
    float bb0[4], bb1[4];
    #pragma unroll
    for (int nt = 0; nt < 4; nt++) {
        bb0[nt] = ba1[8 * nt + 2 * c];
        bb1[nt] = ba1[8 * nt + 2 * c + 1];
    }
    const float b2r0 = ba2[2 * c], b2r1 = ba2[2 * c + 1];

    unsigned* lmW = &LM[warp][0];
    float* attW = &ATT[warp][0];
    const int myh = lane >> 2;
    const int is64 = g_idx_is64;

    for (int b = 0; b < 5; b++) {
        const int ebase = (((blockIdx.x * 4 + warp) * 5) + b) * 32;

        int srcI, dstI;
        if (is64) {
            const long long* ei = (const long long*)edge_index;
            srcI = (int)ei[ebase + lane];
            dstI = (int)ei[EE + ebase + lane];
        } else {
            const int* ei = (const int*)edge_index;
            srcI = ei[ebase + lane];
            dstI = ei[EE + ebase + lane];
        }

        #pragma unroll
        for (int e = 0; e < 32; e++) {
            int s = __shfl_sync(0xffffffffu, srcI, e);
            int d = __shfl_sync(0xffffffffu, dstI, e);
            float2 sv = *(const float2*)(g_src_buf + (size_t)s * FF + 2 * lane);
            float2 dv = *(const float2*)(g_dst_buf + (size_t)d * FF + 2 * lane);
            lmW[e * LMW32 + lane] = pack_bf16(leaky(sv.x + dv.x), leaky(sv.y + dv.y));
        }
        __syncwarp();

        #pragma unroll
        for (int mt = 0; mt < 2; mt++) {
            float acc[4][4];
            #pragma unroll
            for (int nt = 0; nt < 4; nt++)
                acc[nt][0] = acc[nt][1] = acc[nt][2] = acc[nt][3] = 0.0f;

            #pragma unroll
            for (int ks = 0; ks < 4; ks++) {
                unsigned a[4];
                int base = (mt * 16 + r) * LMW32 + 8 * ks + c;
                a[0] = lmW[base];
                a[1] = lmW[base + 8 * LMW32];
                a[2] = lmW[base + 4];
                a[3] = lmW[base + 8 * LMW32 + 4];
                #pragma unroll
                for (int nt = 0; nt < 4; nt++)
                    mma16816(acc[nt], a, w1f[ks][nt]);
            }

            unsigned a2[2][4];
            #pragma unroll
            for (int nt = 0; nt < 4; nt++) {
                float v0 = leaky(acc[nt][0] + bb0[nt]);
                float v1 = leaky(acc[nt][1] + bb1[nt]);
                float v2 = leaky(acc[nt][2] + bb0[nt]);
                float v3 = leaky(acc[nt][3] + bb1[nt]);
                a2[nt >> 1][(nt & 1) * 2 + 0] = pack_bf16(v0, v1);
                a2[nt >> 1][(nt & 1) * 2 + 1] = pack_bf16(v2, v3);
            }

            float z[4] = {0.0f, 0.0f, 0.0f, 0.0f};
            mma16816(z, a2[0], w2f[0]);
            mma16816(z, a2[1], w2f[1]);

            *(float2*)&attW[(mt * 16 + r) * ATTS + 2 * c] =
                make_float2(sigm(z[0] + b2r0), sigm(z[1] + b2r1));
            *(float2*)&attW[(mt * 16 + r + 8) * ATTS + 2 * c] =
                make_float2(sigm(z[2] + b2r0), sigm(z[3] + b2r1));
        }
        __syncwarp();

        #pragma unroll
        for (int e = 0; e < 32; e++) {
            int s = __shfl_sync(0xffffffffu, srcI, e);
            int d = __shfl_sync(0xffffffffu, dstI, e);
            float av = attW[e * ATTS + myh];
            float2 sv = *(const float2*)(g_src_buf + (size_t)s * FF + 2 * lane);
            red2(out + (size_t)d * FF + 2 * lane, av * sv.x, av * sv.y);
        }
        __syncwarp();
    }
}

// ---------------------------------------------------------------------------
extern "C" void kernel_launch(void* const* d_in, const int* in_sizes, int n_in,
                              void* d_out, int out_size)
{
    const float* h      = (const float*)d_in[0];
    const float* W_src  = (const float*)d_in[1];
    const float* b_src  = (const float*)d_in[2];
    const float* W_dst  = (const float*)d_in[3];
    const float* b_dst  = (const float*)d_in[4];
    const float* Wa1_s  = (const float*)d_in[5];
    const float* ba1_s  = (const float*)d_in[6];
    const float* Wa2_s  = (const float*)d_in[7];
    const float* ba2_s  = (const float*)d_in[8];
    const float* Wa1_d  = (const float*)d_in[9];
    const float* ba1_d  = (const float*)d_in[10];
    const float* Wa2_d  = (const float*)d_in[11];
    const float* ba2_d  = (const float*)d_in[12];
    const void*  eidx   = (const void*)d_in[13];
    float* out = (float*)d_out;

    node_kernel<<<(NN + 127) / 128, 128>>>(
        h, W_src, b_src, W_dst, b_dst,
        Wa1_d, ba1_d, Wa2_d, ba2_d,
        (const unsigned int*)eidx, out);

    edge_kernel<<<EE / (4 * 5 * 32), 128>>>(
        eidx, Wa1_s, ba1_s, Wa2_s, ba2_s, out);
}

// round 9
// speedup vs baseline: 3.6131x; 1.0908x over previous
#include <cuda_runtime.h>
#include <cuda_bf16.h>

#define NN 100000
#define FF 64
#define HH 8
#define DD 8
#define EE 1200000
#define HID 32

// scratch (allocation-free rule: __device__ globals)
__device__ float g_src_buf[NN * FF];
__device__ float g_dst_buf[NN * FF];
__device__ int g_idx_is64;

__device__ __forceinline__ float leaky(float x) { return fmaxf(x, 0.2f * x); }
__device__ __forceinline__ float sigm(float x) { return 1.0f / (1.0f + __expf(-x)); }

__device__ __forceinline__ void red4(float* p, float x, float y, float z, float w) {
    asm volatile("red.global.add.v4.f32 [%0], {%1,%2,%3,%4};"
                 :: "l"(p), "f"(x), "f"(y), "f"(z), "f"(w) : "memory");
}

__device__ __forceinline__ unsigned pack_bf16(float lo, float hi) {
    __nv_bfloat162 t = __float22bfloat162_rn(make_float2(lo, hi));
    return *(unsigned*)&t;
}

// split x into bf16 hi + bf16 lo (residual)
__device__ __forceinline__ void split_pack(float a, float b, unsigned& hi, unsigned& lo) {
    __nv_bfloat16 ah = __float2bfloat16(a), bh = __float2bfloat16(b);
    float ar = a - __bfloat162float(ah);
    float br = b - __bfloat162float(bh);
    __nv_bfloat162 t; t.x = ah; t.y = bh;
    hi = *(unsigned*)&t;
    lo = pack_bf16(ar, br);
}

// D += A@B, m16n8k16, bf16 in / fp32 accum
__device__ __forceinline__ void mma16816(float* d, const unsigned* a, const unsigned* b) {
    asm volatile(
        "mma.sync.aligned.m16n8k16.row.col.f32.bf16.bf16.f32 "
        "{%0,%1,%2,%3}, {%4,%5,%6,%7}, {%8,%9}, {%0,%1,%2,%3};"
        : "+f"(d[0]), "+f"(d[1]), "+f"(d[2]), "+f"(d[3])
        : "r"(a[0]), "r"(a[1]), "r"(a[2]), "r"(a[3]), "r"(b[0]), "r"(b[1]));
}

#define LMW32 36               // staging row stride in uint32 (72 bf16), conflict-free
#define ATTS 10                // att row stride

// ---------------------------------------------------------------------------
// Fused node kernel (unchanged from round 7): tensor-core GEMM (hi/lo split)
// + node attention.
__global__ __launch_bounds__(128) void node_kernel(
    const float* __restrict__ h,
    const float* __restrict__ W_src, const float* __restrict__ b_src,
    const float* __restrict__ W_dst, const float* __restrict__ b_dst,
    const float* __restrict__ Wa1, const float* __restrict__ ba1,
    const float* __restrict__ Wa2, const float* __restrict__ ba2,
    const unsigned int* __restrict__ eidx_words,
    float* __restrict__ out)
{
    __shared__ unsigned AHI[128 * LMW32];
    __shared__ unsigned ALO[128 * LMW32];
    __shared__ float ATT[4][32 * ATTS];

    const int tid  = threadIdx.x;
    const int warp = tid >> 5;
    const int lane = tid & 31;
    const int c = lane & 3;
    const int r = lane >> 2;
    const int blockbase = blockIdx.x * 128;

    if (blockIdx.x == 0 && tid == 0) {
        int is64 = 1;
        for (int i = 0; i < 8; i++)
            if (eidx_words[2 * i + 1] != 0u) is64 = 0;
        g_idx_is64 = is64;
    }

    const int mat = warp >> 1;
    const int colbase = 32 * (warp & 1);
    const float* Wm = mat ? W_dst : W_src;
    const float* bm = mat ? b_dst : b_src;

    unsigned bhi[4][4][2], blo[4][4][2];
    #pragma unroll
    for (int ks = 0; ks < 4; ks++)
        #pragma unroll
        for (int nt = 0; nt < 4; nt++) {
            const float* base = Wm + (16 * ks + 2 * c) * FF + colbase + 8 * nt + r;
            split_pack(base[0],       base[FF],     bhi[ks][nt][0], blo[ks][nt][0]);
            split_pack(base[8 * FF],  base[9 * FF], bhi[ks][nt][1], blo[ks][nt][1]);
        }
    float gb0[4], gb1[4];
    #pragma unroll
    for (int nt = 0; nt < 4; nt++) {
        gb0[nt] = bm[colbase + 8 * nt + 2 * c];
        gb1[nt] = bm[colbase + 8 * nt + 2 * c + 1];
    }

    unsigned w1f[4][4][2];
    #pragma unroll
    for (int ks = 0; ks < 4; ks++)
        #pragma unroll
        for (int nt = 0; nt < 4; nt++) {
            const float* base = Wa1 + (16 * ks + 2 * c) * HID + 8 * nt + r;
            w1f[ks][nt][0] = pack_bf16(base[0],        base[HID]);
            w1f[ks][nt][1] = pack_bf16(base[8 * HID],  base[9 * HID]);
        }
    unsigned w2f[2][2];
    #pragma unroll
    for (int ks = 0; ks < 2; ks++) {
        const float* base = Wa2 + (16 * ks + 2 * c) * HH + r;
        w2f[ks][0] = pack_bf16(base[0],      base[HH]);
        w2f[ks][1] = pack_bf16(base[8 * HH], base[9 * HH]);
    }
    float bb0[4], bb1[4];
    #pragma unroll
    for (int nt = 0; nt < 4; nt++) {
        bb0[nt] = ba1[8 * nt + 2 * c];
        bb1[nt] = ba1[8 * nt + 2 * c + 1];
    }
    const float b2r0 = ba2[2 * c], b2r1 = ba2[2 * c + 1];

    #pragma unroll
    for (int e = 0; e < 32; e++) {
        int row = blockbase + 32 * warp + e;
        float2 v = (row < NN) ? *(const float2*)(h + (size_t)row * FF + 2 * lane)
                              : make_float2(0.0f, 0.0f);
        unsigned hv, lv;
        split_pack(v.x, v.y, hv, lv);
        AHI[(32 * warp + e) * LMW32 + lane] = hv;
        ALO[(32 * warp + e) * LMW32 + lane] = lv;
    }
    __syncthreads();

    float* gout = mat ? g_dst_buf : g_src_buf;
    #pragma unroll
    for (int mt = 0; mt < 8; mt++) {
        float acc[4][4];
        #pragma unroll
        for (int nt = 0; nt < 4; nt++)
            acc[nt][0] = acc[nt][1] = acc[nt][2] = acc[nt][3] = 0.0f;

        #pragma unroll
        for (int ks = 0; ks < 4; ks++) {
            int base = (mt * 16 + r) * LMW32 + 8 * ks + c;
            unsigned ah[4], al[4];
            ah[0] = AHI[base];                 al[0] = ALO[base];
            ah[1] = AHI[base + 8 * LMW32];     al[1] = ALO[base + 8 * LMW32];
            ah[2] = AHI[base + 4];             al[2] = ALO[base + 4];
            ah[3] = AHI[base + 8 * LMW32 + 4]; al[3] = ALO[base + 8 * LMW32 + 4];
            #pragma unroll
            for (int nt = 0; nt < 4; nt++) {
                mma16816(acc[nt], ah, blo[ks][nt]);
                mma16816(acc[nt], al, bhi[ks][nt]);
                mma16816(acc[nt], ah, bhi[ks][nt]);
            }
        }

        int row0 = blockbase + 16 * mt + r;
        int row8 = row0 + 8;
        #pragma unroll
        for (int nt = 0; nt < 4; nt++) {
            int col = colbase + 8 * nt + 2 * c;
            if (row0 < NN)
                *(float2*)(gout + (size_t)row0 * FF + col) =
                    make_float2(acc[nt][0] + gb0[nt], acc[nt][1] + gb1[nt]);
            if (row8 < NN)
                *(float2*)(gout + (size_t)row8 * FF + col) =
                    make_float2(acc[nt][2] + gb0[nt], acc[nt][3] + gb1[nt]);
        }
    }
    __syncthreads();

    const int nbase = blockbase + 32 * warp;
    if (nbase >= NN) return;

    unsigned* lmW = &AHI[(32 * warp) * LMW32];
    float* attW = &ATT[warp][0];
    const int myh = lane >> 2;

    #pragma unroll
    for (int e = 0; e < 32; e++) {
        float2 dv = *(const float2*)(g_dst_buf + (size_t)(nbase + e) * FF + 2 * lane);
        lmW[e * LMW32 + lane] = pack_bf16(leaky(dv.x), leaky(dv.y));
    }
    __syncwarp();

    #pragma unroll
    for (int mt = 0; mt < 2; mt++) {
        float acc[4][4];
        #pragma unroll
        for (int nt = 0; nt < 4; nt++)
            acc[nt][0] = acc[nt][1] = acc[nt][2] = acc[nt][3] = 0.0f;

        #pragma unroll
        for (int ks = 0; ks < 4; ks++) {
            unsigned a[4];
            int base = (mt * 16 + r) * LMW32 + 8 * ks + c;
            a[0] = lmW[base];
            a[1] = lmW[base + 8 * LMW32];
            a[2] = lmW[base + 4];
            a[3] = lmW[base + 8 * LMW32 + 4];
            #pragma unroll
            for (int nt = 0; nt < 4; nt++)
                mma16816(acc[nt], a, w1f[ks][nt]);
        }

        unsigned a2[2][4];
        #pragma unroll
        for (int nt = 0; nt < 4; nt++) {
            float v0 = leaky(acc[nt][0] + bb0[nt]);
            float v1 = leaky(acc[nt][1] + bb1[nt]);
            float v2 = leaky(acc[nt][2] + bb0[nt]);
            float v3 = leaky(acc[nt][3] + bb1[nt]);
            a2[nt >> 1][(nt & 1) * 2 + 0] = pack_bf16(v0, v1);
            a2[nt >> 1][(nt & 1) * 2 + 1] = pack_bf16(v2, v3);
        }

        float z[4] = {0.0f, 0.0f, 0.0f, 0.0f};
        mma16816(z, a2[0], w2f[0]);
        mma16816(z, a2[1], w2f[1]);

        *(float2*)&attW[(mt * 16 + r) * ATTS + 2 * c] =
            make_float2(sigm(z[0] + b2r0), sigm(z[1] + b2r1));
        *(float2*)&attW[(mt * 16 + r + 8) * ATTS + 2 * c] =
            make_float2(sigm(z[2] + b2r0), sigm(z[3] + b2r1));
    }
    __syncwarp();

    #pragma unroll
    for (int e = 0; e < 32; e++) {
        float av = attW[e * ATTS + myh];
        float2 dv = *(const float2*)(g_dst_buf + (size_t)(nbase + e) * FF + 2 * lane);
        *(float2*)(out + (size_t)(nbase + e) * FF + 2 * lane) =
            make_float2(av * dv.x, av * dv.y);
    }
}

// ---------------------------------------------------------------------------
// Edge kernel v4: float4 half-warp rows + cross-batch pipeline.
// Lanes 0-15 cover edge 2i, lanes 16-31 edge 2i+1, 16B per lane.
// Per batch: gather (LDG.128 x2/iter) -> MMA MLP -> scatter (red.v4),
// with scatter(b) interleaved with gather(b+1) to overlap latencies.
__global__ __launch_bounds__(128) void edge_kernel(
    const void* __restrict__ edge_index,
    const float* __restrict__ Wa1, const float* __restrict__ ba1,
    const float* __restrict__ Wa2, const float* __restrict__ ba2,
    float* __restrict__ out)
{
    __shared__ unsigned LM[4][32 * LMW32];
    __shared__ float ATT[4][32 * ATTS];

    const int tid  = threadIdx.x;
    const int warp = tid >> 5;
    const int lane = tid & 31;
    const int c = lane & 3;
    const int r = lane >> 2;
    const int half = lane >> 4;      // which edge of the pair
    const int sub  = lane & 15;      // 16B chunk within row
    const int myh4 = sub >> 1;       // head for floats [4sub, 4sub+3]

    unsigned w1f[4][4][2];
    #pragma unroll
    for (int ks = 0; ks < 4; ks++)
        #pragma unroll
        for (int nt = 0; nt < 4; nt++) {
            const float* base = Wa1 + (16 * ks + 2 * c) * HID + 8 * nt + r;
            w1f[ks][nt][0] = pack_bf16(base[0],        base[HID]);
            w1f[ks][nt][1] = pack_bf16(base[8 * HID],  base[9 * HID]);
        }
    unsigned w2f[2][2];
    #pragma unroll
    for (int ks = 0; ks < 2; ks++) {
        const float* base = Wa2 + (16 * ks + 2 * c) * HH + r;
        w2f[ks][0] = pack_bf16(base[0],      base[HH]);
        w2f[ks][1] = pack_bf16(base[8 * HH], base[9 * HH]);
    }
    float bb0[4], bb1[4];
    #pragma unroll
    for (int nt = 0; nt < 4; nt++) {
        bb0[nt] = ba1[8 * nt + 2 * c];
        bb1[nt] = ba1[8 * nt + 2 * c + 1];
    }
    const float b2r0 = ba2[2 * c], b2r1 = ba2[2 * c + 1];

    unsigned* lmW = &LM[warp][0];
    float* attW = &ATT[warp][0];
    const int is64 = g_idx_is64;
    const int wbase = (blockIdx.x * 4 + warp) * 5;

    // load indices for batch b into lane-held registers
    auto load_idx = [&](int b, int& sI, int& dI) {
        const int ebase = (wbase + b) * 32;
        if (is64) {
            const long long* ei = (const long long*)edge_index;
            sI = (int)ei[ebase + lane];
            dI = (int)ei[EE + ebase + lane];
        } else {
            const int* ei = (const int*)edge_index;
            sI = ei[ebase + lane];
            dI = ei[EE + ebase + lane];
        }
    };

    int srcA, dstA;           // current batch
    load_idx(0, srcA, dstA);

    // gather batch 0
    #pragma unroll
    for (int i = 0; i < 16; i++) {
        int e = 2 * i + half;
        int s = __shfl_sync(0xffffffffu, srcA, e);
        int d = __shfl_sync(0xffffffffu, dstA, e);
        float4 sv = *(const float4*)(g_src_buf + (size_t)s * FF + 4 * sub);
        float4 dv = *(const float4*)(g_dst_buf + (size_t)d * FF + 4 * sub);
        unsigned p0 = pack_bf16(leaky(sv.x + dv.x), leaky(sv.y + dv.y));
        unsigned p1 = pack_bf16(leaky(sv.z + dv.z), leaky(sv.w + dv.w));
        *(uint2*)&lmW[e * LMW32 + 2 * sub] = make_uint2(p0, p1);
    }

    for (int b = 0; b < 5; b++) {
        __syncwarp();

        // ---- MMA MLP on batch b ----
        #pragma unroll
        for (int mt = 0; mt < 2; mt++) {
            float acc[4][4];
            #pragma unroll
            for (int nt = 0; nt < 4; nt++)
                acc[nt][0] = acc[nt][1] = acc[nt][2] = acc[nt][3] = 0.0f;

            #pragma unroll
            for (int ks = 0; ks < 4; ks++) {
                unsigned a[4];
                int base = (mt * 16 + r) * LMW32 + 8 * ks + c;
                a[0] = lmW[base];
                a[1] = lmW[base + 8 * LMW32];
                a[2] = lmW[base + 4];
                a[3] = lmW[base + 8 * LMW32 + 4];
                #pragma unroll
                for (int nt = 0; nt < 4; nt++)
                    mma16816(acc[nt], a, w1f[ks][nt]);
            }

            unsigned a2[2][4];
            #pragma unroll
            for (int nt = 0; nt < 4; nt++) {
                float v0 = leaky(acc[nt][0] + bb0[nt]);
                float v1 = leaky(acc[nt][1] + bb1[nt]);
                float v2 = leaky(acc[nt][2] + bb0[nt]);
                float v3 = leaky(acc[nt][3] + bb1[nt]);
                a2[nt >> 1][(nt & 1) * 2 + 0] = pack_bf16(v0, v1);
                a2[nt >> 1][(nt & 1) * 2 + 1] = pack_bf16(v2, v3);
            }

            float z[4] = {0.0f, 0.0f, 0.0f, 0.0f};
            mma16816(z, a2[0], w2f[0]);
            mma16816(z, a2[1], w2f[1]);

            *(float2*)&attW[(mt * 16 + r) * ATTS + 2 * c] =
                make_float2(sigm(z[0] + b2r0), sigm(z[1] + b2r1));
            *(float2*)&attW[(mt * 16 + r + 8) * ATTS + 2 * c] =
                make_float2(sigm(z[2] + b2r0), sigm(z[3] + b2r1));
        }
        __syncwarp();

        // ---- interleaved: gather(b+1) + scatter(b) ----
        int srcN, dstN;
        const bool more = (b < 4);
        if (more) load_idx(b + 1, srcN, dstN);

        #pragma unroll
        for (int i = 0; i < 16; i++) {
            int e = 2 * i + half;
            if (more) {
                int s = __shfl_sync(0xffffffffu, srcN, e);
                int d = __shfl_sync(0xffffffffu, dstN, e);
                float4 sv = *(const float4*)(g_src_buf + (size_t)s * FF + 4 * sub);
                float4 dv = *(const float4*)(g_dst_buf + (size_t)d * FF + 4 * sub);
                unsigned p0 = pack_bf16(leaky(sv.x + dv.x), leaky(sv.y + dv.y));
                unsigned p1 = pack_bf16(leaky(sv.z + dv.z), leaky(sv.w + dv.w));
                *(uint2*)&lmW[e * LMW32 + 2 * sub] = make_uint2(p0, p1);
            }
            {
                int s = __shfl_sync(0xffffffffu, srcA, e);
                int d = __shfl_sync(0xffffffffu, dstA, e);
                float av = attW[e * ATTS + myh4];
                float4 sv = *(const float4*)(g_src_buf + (size_t)s * FF + 4 * sub);
                red4(out + (size_t)d * FF + 4 * sub,
                     av * sv.x, av * sv.y, av * sv.z, av * sv.w);
            }
        }
        srcA = srcN; dstA = dstN;
    }
}

// ---------------------------------------------------------------------------
extern "C" void kernel_launch(void* const* d_in, const int* in_sizes, int n_in,
                              void* d_out, int out_size)
{
    const float* h      = (const float*)d_in[0];
    const float* W_src  = (const float*)d_in[1];
    const float* b_src  = (const float*)d_in[2];
    const float* W_dst  = (const float*)d_in[3];
    const float* b_dst  = (const float*)d_in[4];
    const float* Wa1_s  = (const float*)d_in[5];
    const float* ba1_s  = (const float*)d_in[6];
    const float* Wa2_s  = (const float*)d_in[7];
    const float* ba2_s  = (const float*)d_in[8];
    const float* Wa1_d  = (const float*)d_in[9];
    const float* ba1_d  = (const float*)d_in[10];
    const float* Wa2_d  = (const float*)d_in[11];
    const float* ba2_d  = (const float*)d_in[12];
    const void*  eidx   = (const void*)d_in[13];
    float* out = (float*)d_out;

    node_kernel<<<(NN + 127) / 128, 128>>>(
        h, W_src, b_src, W_dst, b_dst,
        Wa1_d, ba1_d, Wa2_d, ba2_d,
        (const unsigned int*)eidx, out);

    edge_kernel<<<EE / (4 * 5 * 32), 128>>>(
        eidx, Wa1_s, ba1_s, Wa2_s, ba2_s, out);
}